// round 13
// baseline (speedup 1.0000x reference)
#include <cuda_runtime.h>
#include <math.h>
#include <cstdint>

#define SEQ 4096
#define DM  1024
#define NH  16
#define HD  64

#if !defined(__CUDA_ARCH__) || defined(__CUDA_ARCH_FEAT_SM103_ALL) || \
    defined(__CUDA_ARCH_FEAT_SM100_ALL) || defined(__CUDA_ARCH_FEAT_SM101_ALL)
#define TC_OK 1
#else
#define TC_OK 0
#endif

// ---------------- scratch ---------------------------------------------------
// xt, Wt, AO live in BLOCKED layout: tile (rb, kc) = rows rb*128..+127,
// cols kc*32..+31, contiguous 16KB with SW128 swizzle pre-applied.
__device__ float g_Q[SEQ * DM];        // [h][s][hd], tf32-rounded, *0.125*log2e
__device__ float g_K[SEQ * DM];        // [h][s][hd], tf32-rounded
__device__ float g_V[SEQ * DM];        // V^T per head [h][d][s], tf32-rounded
__device__ float g_AO[SEQ * DM];       // attention out, BLOCKED, tf32-rounded
__device__ float g_xt[SEQ * DM];       // x, BLOCKED, tf32-rounded
__device__ float g_Wt[4 * DM * DM];    // weights, BLOCKED, tf32-rounded
__device__ float g_invf[32];
__device__ float g_cosT[32 * SEQ];
__device__ float g_sinT[32 * SEQ];

// ---------------- PTX helpers ----------------------------------------------
__device__ __forceinline__ uint32_t smem_u32(const void* p) {
    uint32_t a;
    asm("{ .reg .u64 t; cvta.to.shared.u64 t, %1; cvt.u32.u64 %0, t; }"
        : "=r"(a) : "l"(p));
    return a;
}
__device__ __forceinline__ uint32_t elect_one() {
    uint32_t pred;
    asm volatile("{\n\t.reg .pred p;\n\telect.sync _|p, 0xFFFFFFFF;\n\t"
                 "selp.b32 %0, 1, 0, p;\n\t}" : "=r"(pred));
    return pred;
}
#define TC_ALLOC(smem_addr, n) \
    asm volatile("tcgen05.alloc.cta_group::1.sync.aligned.shared::cta.b32 [%0], %1;" \
                 :: "r"(smem_addr), "r"(n) : "memory")
#define TC_DEALLOC(tmem, n) \
    asm volatile("tcgen05.dealloc.cta_group::1.sync.aligned.b32 %0, %1;" :: "r"(tmem), "r"(n))
#define TC_RELINQ() \
    asm volatile("tcgen05.relinquish_alloc_permit.cta_group::1.sync.aligned;")
#define TC_COMMIT(mbar) \
    asm volatile("tcgen05.commit.cta_group::1.mbarrier::arrive::one.shared::cluster.b64 [%0];" \
                 :: "r"(mbar) : "memory")
#define TC_FENCE_AFTER()  asm volatile("tcgen05.fence::after_thread_sync;" ::: "memory")
#define TC_FENCE_BEFORE() asm volatile("tcgen05.fence::before_thread_sync;" ::: "memory")
#define TC_WAIT_LD()      asm volatile("tcgen05.wait::ld.sync.aligned;" ::: "memory")
#define TC_WAIT_ST()      asm volatile("tcgen05.wait::st.sync.aligned;" ::: "memory")
#define FENCE_ASYNC()     asm volatile("fence.proxy.async.shared::cta;" ::: "memory")
#define MBAR_INIT(a, c) \
    asm volatile("mbarrier.init.shared.b64 [%0], %1;" :: "r"(a), "r"(c) : "memory")
#define MBAR_INVAL(a) \
    asm volatile("mbarrier.inval.shared.b64 [%0];" :: "r"(a) : "memory")
#define MBAR_WAIT(addr, ph) do {                                              \
    uint32_t _m = (addr), _p = (ph), _d;                                      \
    asm volatile("{\n\t.reg .pred p;\n\t"                                     \
        "mbarrier.try_wait.parity.acquire.cta.shared::cta.b64 p, [%1], %2;\n\t" \
        "selp.b32 %0, 1, 0, p;\n\t}" : "=r"(_d) : "r"(_m), "r"(_p) : "memory"); \
    if (!_d) {                                                                \
        asm volatile("{\n\t.reg .pred P1;\n\tWL_%=: \n\t"                     \
            "mbarrier.try_wait.parity.acquire.cta.shared::cta.b64 P1, [%0], %1, 0x989680;\n\t" \
            "@P1 bra.uni WD_%=;\n\tbra.uni WL_%=;\n\tWD_%=:\n\t}"             \
            :: "r"(_m), "r"(_p) : "memory");                                  \
    }                                                                         \
} while (0)
#define LDTM_X32(r, tmem_addr) \
    asm volatile("tcgen05.ld.sync.aligned.32x32b.x32.b32 " \
        "{%0, %1, %2, %3, %4, %5, %6, %7, %8, %9, %10, %11, %12, %13, %14, %15, " \
        "%16, %17, %18, %19, %20, %21, %22, %23, %24, %25, %26, %27, %28, %29, %30, %31}, [%32];" \
        : "=r"((r)[0]),  "=r"((r)[1]),  "=r"((r)[2]),  "=r"((r)[3]),  \
          "=r"((r)[4]),  "=r"((r)[5]),  "=r"((r)[6]),  "=r"((r)[7]),  \
          "=r"((r)[8]),  "=r"((r)[9]),  "=r"((r)[10]), "=r"((r)[11]), \
          "=r"((r)[12]), "=r"((r)[13]), "=r"((r)[14]), "=r"((r)[15]), \
          "=r"((r)[16]), "=r"((r)[17]), "=r"((r)[18]), "=r"((r)[19]), \
          "=r"((r)[20]), "=r"((r)[21]), "=r"((r)[22]), "=r"((r)[23]), \
          "=r"((r)[24]), "=r"((r)[25]), "=r"((r)[26]), "=r"((r)[27]), \
          "=r"((r)[28]), "=r"((r)[29]), "=r"((r)[30]), "=r"((r)[31]) \
        : "r"(tmem_addr))
#define STTM_X32(tmem_addr, r) \
    asm volatile("tcgen05.st.sync.aligned.32x32b.x32.b32 [%0], " \
        "{%1, %2, %3, %4, %5, %6, %7, %8, %9, %10, %11, %12, %13, %14, %15, %16, " \
        "%17, %18, %19, %20, %21, %22, %23, %24, %25, %26, %27, %28, %29, %30, %31, %32};" \
        :: "r"(tmem_addr), \
           "r"((r)[0]),  "r"((r)[1]),  "r"((r)[2]),  "r"((r)[3]),  \
           "r"((r)[4]),  "r"((r)[5]),  "r"((r)[6]),  "r"((r)[7]),  \
           "r"((r)[8]),  "r"((r)[9]),  "r"((r)[10]), "r"((r)[11]), \
           "r"((r)[12]), "r"((r)[13]), "r"((r)[14]), "r"((r)[15]), \
           "r"((r)[16]), "r"((r)[17]), "r"((r)[18]), "r"((r)[19]), \
           "r"((r)[20]), "r"((r)[21]), "r"((r)[22]), "r"((r)[23]), \
           "r"((r)[24]), "r"((r)[25]), "r"((r)[26]), "r"((r)[27]), \
           "r"((r)[28]), "r"((r)[29]), "r"((r)[30]), "r"((r)[31]) \
        : "memory")
#define CP_ASYNC16(smem, gptr) \
    asm volatile("cp.async.cg.shared.global [%0], [%1], 16;" \
                 :: "r"(smem), "l"(gptr) : "memory")
#define CP_COMMIT() asm volatile("cp.async.commit_group;" ::: "memory")
#define CP_WAIT(n)  asm volatile("cp.async.wait_group %0;" :: "n"(n) : "memory")

static constexpr uint64_t DESC_BASE_SW128 =
    (uint64_t(2) << 61) | (uint64_t(1) << 46) | (uint64_t(64) << 32) | (uint64_t(1) << 16);
#define MK_DESC(addr) (DESC_BASE_SW128 | ((uint64_t)((addr) >> 4) & 0x3FFF))
#define SWZ128(off) ((off) ^ (((off) >> 3) & 0x70))

#if TC_OK
__device__ __forceinline__ void mma_tf32_ss(uint32_t d, uint64_t ad, uint64_t bd,
                                            uint32_t idesc, uint32_t en) {
    asm volatile("{\n\t.reg .pred p;\n\tsetp.ne.u32 p, %5, 0;\n\t"
        "tcgen05.mma.cta_group::1.kind::tf32 [%0], %1, %2, %3, {%4, %4, %4, %4}, p;\n\t}"
        :: "r"(d), "l"(ad), "l"(bd), "r"(idesc), "r"(0u), "r"(en) : "memory");
}
__device__ __forceinline__ void mma_tf32_ts(uint32_t d, uint32_t a_tmem, uint64_t bd,
                                            uint32_t idesc, uint32_t en) {
    asm volatile("{\n\t.reg .pred p;\n\tsetp.ne.u32 p, %5, 0;\n\t"
        "tcgen05.mma.cta_group::1.kind::tf32 [%0], [%1], %2, %3, {%4, %4, %4, %4}, p;\n\t}"
        :: "r"(d), "r"(a_tmem), "l"(bd), "r"(idesc), "r"(0u), "r"(en) : "memory");
}
#endif

__device__ __forceinline__ float tf32r(float x) {
    uint32_t u;
    asm("cvt.rna.tf32.f32 %0, %1;" : "=r"(u) : "f"(x));
    return __uint_as_float(u);
}
__device__ __forceinline__ float ex2f(float x) {
    float y;
    asm("ex2.approx.f32 %0, %1;" : "=f"(y) : "f"(x));
    return y;
}

static constexpr uint32_t IDESC_N128 =
    (1u << 4) | (2u << 7) | (2u << 10) | (16u << 17) | (8u << 24);
static constexpr uint32_t IDESC_N64 =
    (1u << 4) | (2u << 7) | (2u << 10) | (8u << 17) | (8u << 24);

// (1/sqrt(64)) * log2(e)
#define QSCALE 0.18033688011112042f

__host__ __device__ __forceinline__ uint32_t blk_off(int r, int c) {
    return ((uint32_t)(r >> 7) * 32 + (uint32_t)(c >> 5)) * 16384u +
           SWZ128((uint32_t)((r & 127) << 7) + (uint32_t)((c & 31) << 2));
}

// ---------------- init / precvt ---------------------------------------------
__global__ void init_invf() {
    int j = threadIdx.x;
    double e = (double)(2 * j) / 64.0;
    g_invf[j] = (float)(1.0 / pow(10000.0, e));
}
__global__ __launch_bounds__(256) void init_tables() {
    int idx = blockIdx.x * blockDim.x + threadIdx.x;
    int j = idx >> 12;
    int s = idx & (SEQ - 1);
    float ang = (float)s * g_invf[j];
    float sn, cs;
    sincosf(ang, &sn, &cs);
    g_cosT[idx] = cs;
    g_sinT[idx] = sn;
}
__global__ __launch_bounds__(256) void precvt_all(
    const float* __restrict__ x,
    const float* __restrict__ Wq, const float* __restrict__ Wk,
    const float* __restrict__ Wv, const float* __restrict__ Wo,
    float* __restrict__ xt, float* __restrict__ Wt)
{
    int i = blockIdx.x * 256 + threadIdx.x;
    const float4* src;
    char* dstbase;
    int off;
    if (i < (1 << 20)) {
        src = (const float4*)x; dstbase = (char*)xt; off = i;
    } else {
        int k = i - (1 << 20);
        int w = k >> 18;
        off = k & ((1 << 18) - 1);
        src = (const float4*)(w == 0 ? Wq : w == 1 ? Wk : w == 2 ? Wv : Wo);
        dstbase = (char*)(Wt + (size_t)w * DM * DM);
    }
    float4 v = src[off];
    v.x = tf32r(v.x); v.y = tf32r(v.y); v.z = tf32r(v.z); v.w = tf32r(v.w);
    int r = off >> 8;
    int c4 = off & 255;
    uint32_t byte = ((uint32_t)(r >> 7) * 32 + (uint32_t)(c4 >> 3)) * 16384u +
                    SWZ128((uint32_t)((r & 127) << 7) + (uint32_t)((c4 & 7) << 4));
    *(float4*)(dstbase + byte) = v;
}

// ---------------------------------------------------------------------------
// tcgen05 tf32 GEMM, 128x128 tile, BLOCKED inputs. 256-thread cp.async feed
// with LINEAR offsets (tiles pre-swizzled -> straight memcpy), 3 stages,
// 2 CTAs/SM, one wave. R9-proven sync structure.
// mode: bit0 head layout; bit1 RoPE; bit2 V^T; bit3 tf32-round; bit4 scale.
// ---------------------------------------------------------------------------
#define GEMM_SMEM 100352

__global__ __launch_bounds__(256, 2) void gemm_tc(
    const float* __restrict__ A, const float* __restrict__ B,
    const float* __restrict__ bias, float* __restrict__ C, int mode, float sc,
    const float* __restrict__ cosT, const float* __restrict__ sinT)
{
#if TC_OK
    extern __shared__ char sm[];
    const uint32_t sbase = smem_u32(sm);
    const uint32_t tile0 = (sbase + 64 + 1023) & ~1023u;

    const int tid = threadIdx.x;
    const int wid = tid >> 5;
    const int row0 = blockIdx.y << 7;
    const int col0 = blockIdx.x << 7;

    if (wid == 0) TC_ALLOC(sbase, 128);
    if (tid == 0) {
        MBAR_INIT(sbase + 8, 1);  MBAR_INIT(sbase + 16, 1);
        MBAR_INIT(sbase + 24, 1);
    }
    __syncthreads();
    uint32_t tmem;
    asm volatile("ld.shared.b32 %0, [%1];" : "=r"(tmem) : "r"(sbase));
    if (wid == 0) TC_RELINQ();

    const char* Asrc = (const char*)A + (size_t)(row0 >> 7) * 32 * 16384;
    const char* Bsrc = (const char*)B + (size_t)(col0 >> 7) * 32 * 16384;

    for (int kc = 0; kc < 34; kc++) {
        if (kc < 32) {
            const int s = kc % 3;
            if (kc >= 3) MBAR_WAIT(sbase + 8 + s * 8, ((kc - 3) / 3) & 1);
            const uint32_t sA = tile0 + s * 32768;
            const char* Ag = Asrc + (size_t)kc * 16384;
            const char* Bg = Bsrc + (size_t)kc * 16384;
#pragma unroll
            for (int t = 0; t < 4; t++) {
                uint32_t off = (uint32_t)tid * 16 + t * 4096;
                CP_ASYNC16(sA + off, Ag + off);
                CP_ASYNC16(sA + 16384 + off, Bg + off);
            }
            CP_COMMIT();
        }
        if (kc >= 2) {
            const int j = kc - 2;
            const int sj = j % 3;
            if (kc < 32) CP_WAIT(2);
            else if (kc == 32) CP_WAIT(1);
            else CP_WAIT(0);
            __syncthreads();
            if (wid == 0 && elect_one()) {
                FENCE_ASYNC();
                uint64_t ad = MK_DESC(tile0 + sj * 32768);
                uint64_t bd = MK_DESC(tile0 + sj * 32768 + 16384);
#pragma unroll
                for (int ks = 0; ks < 4; ks++)
                    mma_tf32_ss(tmem, ad + ks * 2, bd + ks * 2, IDESC_N128,
                                (j > 0) || (ks > 0));
                TC_COMMIT(sbase + 8 + sj * 8);
            }
        }
    }
    MBAR_WAIT(sbase + 8, 0);
    MBAR_WAIT(sbase + 16, 0);
    MBAR_WAIT(sbase + 24, 1);
    TC_FENCE_AFTER();

    if (tid < 128) {
        const int lid = tid & 31;
        const int w = tid >> 5;
        const int row = row0 + w * 32 + lid;
        const bool rope = (mode & 2) != 0;
        const bool rnd  = (mode & 8) != 0;
        const bool scl  = (mode & 16) != 0;
#pragma unroll
        for (int half = 0; half < 2; half++) {
            uint32_t rr[64];
            LDTM_X32(rr, tmem + half * 64);
            LDTM_X32(rr + 32, tmem + half * 64 + 32);
            TC_WAIT_LD();
            const int gc0 = col0 + half * 64;
            float v[64];
#pragma unroll
            for (int j = 0; j < 64; j++)
                v[j] = __uint_as_float(rr[j]) + __ldg(&bias[gc0 + j]);
            if (rope) {
#pragma unroll
                for (int j = 0; j < 32; j++) {
                    float cs = __ldg(&cosT[j * SEQ + row]);
                    float sn = __ldg(&sinT[j * SEQ + row]);
                    float a = v[j], b2 = v[j + 32];
                    v[j]      = a * cs - b2 * sn;
                    v[j + 32] = b2 * cs + a * sn;
                }
            }
            if (scl) {
#pragma unroll
                for (int j = 0; j < 64; j++) v[j] *= sc;
            }
            if (rnd) {
#pragma unroll
                for (int j = 0; j < 64; j++) v[j] = tf32r(v[j]);
            }
            if (mode & 4) {
                int hh = gc0 >> 6;
                float* dst = C + (size_t)(hh * HD) * SEQ + row;
#pragma unroll
                for (int j = 0; j < 64; j++)
                    dst[(size_t)j * SEQ] = v[j];
            } else if (mode & 1) {
                int hh = gc0 >> 6;
                float* dst = C + ((size_t)hh * SEQ + row) * HD;
#pragma unroll
                for (int j4 = 0; j4 < 64; j4 += 4)
                    *(float4*)(dst + j4) = make_float4(v[j4], v[j4+1], v[j4+2], v[j4+3]);
            } else {
                float* dst = C + (size_t)row * DM + gc0;
#pragma unroll
                for (int j4 = 0; j4 < 64; j4 += 4)
                    *(float4*)(dst + j4) = make_float4(v[j4], v[j4+1], v[j4+2], v[j4+3]);
            }
        }
    }
    __syncthreads();
    if (tid == 0) {
        MBAR_INVAL(sbase + 8);  MBAR_INVAL(sbase + 16);
        MBAR_INVAL(sbase + 24);
    }
    __syncthreads();
    if (wid == 0) TC_DEALLOC(tmem, 128);
#else
    const int tid = threadIdx.x;
    const int row0 = blockIdx.y << 7;
    const int col0 = blockIdx.x << 7;
    for (int e = tid; e < 128 * 128; e += 256) {
        int r = row0 + (e >> 7);
        int c = col0 + (e & 127);
        float acc = bias[c];
        for (int k = 0; k < DM; k++)
            acc += *(const float*)((const char*)A + blk_off(r, k)) *
                   *(const float*)((const char*)B + blk_off(c, k));
        float outv = acc;
        if (mode & 2) {
            int j = c & 63;
            int jp = (j < 32) ? j + 32 : j - 32;
            int cp = (c & ~63) | jp;
            float acc2 = bias[cp];
            for (int k = 0; k < DM; k++)
                acc2 += *(const float*)((const char*)A + blk_off(r, k)) *
                        *(const float*)((const char*)B + blk_off(cp, k));
            int f = (j < 32) ? j : j - 32;
            float cs = cosT[f * SEQ + r], sn = sinT[f * SEQ + r];
            outv = (j < 32) ? (acc * cs - acc2 * sn) : (acc * cs + acc2 * sn);
        }
        if (mode & 16) outv *= sc;
        if (mode & 8)  outv = tf32r(outv);
        if (mode & 4)      C[(size_t)((c >> 6) * HD + (c & 63)) * SEQ + r] = outv;
        else if (mode & 1) C[(((size_t)(c >> 6) * SEQ + r) * HD) + (c & 63)] = outv;
        else               C[(size_t)r * DM + c] = outv;
    }
#endif
}

// ---------------------------------------------------------------------------
// tcgen05 flash attention (tf32), causal, no-max exp2 softmax — PROVEN R11
// version: tf32r'd P, lp accumulation, lsum smem combine, blocked AO store.
// S(kt+1) issued at top of iter kt; LDTM(c1) in flight under ex2(c0);
// diag/non-diag split. P in TMEM; PV = TS-form MMA.
// TMEM: S0 @0 | S1 @128 | O @256 | P @320.
// ---------------------------------------------------------------------------
#if TC_OK
#define ATTN_SMEM 166912
#else
#define ATTN_SMEM 0
#endif

__global__ __launch_bounds__(256) void attn_tc(
    const float* __restrict__ Q, const float* __restrict__ K,
    const float* __restrict__ Vt, float* __restrict__ Og)
{
#if TC_OK
    extern __shared__ char sm[];
    const uint32_t sbase = smem_u32(sm);
    float* lsum = (float*)(sm + 64);                 // [2][128]
    const uint32_t tile0 = (sbase + 1088 + 1023) & ~1023u;
    const uint32_t QS  = tile0;
    const uint32_t KS0 = tile0 + 32768;
    const uint32_t VS0 = tile0 + 98304;

    const int qt = (int)gridDim.x - 1 - (int)blockIdx.x;
    const int h  = blockIdx.y;
    const int nt = qt + 1;
    const int tid = threadIdx.x;
    const int wid = tid >> 5;
    const int lane = tid & 31;
    const int g = wid >> 2;
    const int rowl = ((wid & 3) << 5) + lane;
    const int cbase = g << 6;
    const uint32_t laneoff = ((uint32_t)(wid & 3)) << 21;

    if (wid == 0) TC_ALLOC(sbase, 512);
    if (tid == 0) {
        MBAR_INIT(sbase + 8, 1);
        MBAR_INIT(sbase + 16, 1);
        MBAR_INIT(sbase + 24, 1);
    }
    __syncthreads();
    uint32_t tmem;
    asm volatile("ld.shared.b32 %0, [%1];" : "=r"(tmem) : "r"(sbase));
    if (wid == 0) TC_RELINQ();
    const uint32_t tmO = tmem + 256;
    const uint32_t tmP = tmem + 320;

    const float* Qg  = Q + ((size_t)h * SEQ + (size_t)qt * 128) * HD;
    const float* Kg0 = K + (size_t)h * SEQ * HD;
    const float* Vg0 = Vt + (size_t)(h * HD) * SEQ;
    const uint64_t adQ = MK_DESC(QS);

    // ---- prologue: Q, K(0), V(0); K(1)
#pragma unroll
    for (int i = 0; i < 8; i++) {
        int idx = tid + i * 256;
        int r = idx >> 4, c4 = idx & 15;
        uint32_t off = ((uint32_t)(c4 >> 3) * 16384) +
                       SWZ128((uint32_t)(r * 128 + (c4 & 7) * 16));
        CP_ASYNC16(QS + off, Qg + (size_t)r * HD + c4 * 4);
        CP_ASYNC16(KS0 + off, Kg0 + (size_t)r * HD + c4 * 4);
    }
#pragma unroll
    for (int i = 0; i < 8; i++) {
        int idx = tid + i * 256;
        int r = idx >> 5, c4 = idx & 31;
        uint32_t off = ((uint32_t)(c4 >> 3) * 8192) +
                       SWZ128((uint32_t)(r * 128 + (c4 & 7) * 16));
        CP_ASYNC16(VS0 + off, Vg0 + (size_t)r * SEQ + c4 * 4);
    }
    CP_COMMIT();
    if (nt > 1) {
        const float* Kg = Kg0 + (size_t)128 * HD;
#pragma unroll
        for (int i = 0; i < 8; i++) {
            int idx = tid + i * 256;
            int r = idx >> 4, c4 = idx & 15;
            uint32_t off = ((uint32_t)(c4 >> 3) * 16384) +
                           SWZ128((uint32_t)(r * 128 + (c4 & 7) * 16));
            CP_ASYNC16(KS0 + 32768 + off, Kg + (size_t)r * HD + c4 * 4);
        }
        CP_COMMIT();
    }
    CP_WAIT(0);
    __syncthreads();
    if (wid == 0 && elect_one()) {
        FENCE_ASYNC();
        uint64_t bd = MK_DESC(KS0);
#pragma unroll
        for (int ks = 0; ks < 8; ks++)
            mma_tf32_ss(tmem, adQ + (ks >> 2) * 1024 + (ks & 3) * 2,
                        bd + (ks >> 2) * 1024 + (ks & 3) * 2, IDESC_N128, ks > 0);
        TC_COMMIT(sbase + 8);
    }

    float lp = 0.0f;

    for (int kt = 0; kt < nt; kt++) {
        const int b = kt & 1;
        const uint32_t tmSb = tmem + (uint32_t)b * 128;

        MBAR_WAIT(sbase + 8 + b * 8, (kt >> 1) & 1);   // S(kt) ready
        TC_FENCE_AFTER();

        // issue S(kt+1) now (overlaps softmax below)
        if (kt + 1 < nt && wid == 0 && elect_one()) {
            FENCE_ASYNC();
            uint64_t bd = MK_DESC(KS0 + (uint32_t)(b ^ 1) * 32768);
            uint32_t d = tmem + (uint32_t)(b ^ 1) * 128;
#pragma unroll
            for (int ks = 0; ks < 8; ks++)
                mma_tf32_ss(d, adQ + (ks >> 2) * 1024 + (ks & 3) * 2,
                            bd + (ks >> 2) * 1024 + (ks & 3) * 2,
                            IDESC_N128, ks > 0);
            TC_COMMIT(sbase + 8 + (b ^ 1) * 8);
        }

        // prefetch K(kt+2) into Kbuf[b]
        if (kt + 2 < nt) {
            const float* Kg = Kg0 + (size_t)(kt + 2) * 128 * HD;
#pragma unroll
            for (int i = 0; i < 8; i++) {
                int idx = tid + i * 256;
                int r = idx >> 4, c4 = idx & 15;
                uint32_t off = ((uint32_t)(c4 >> 3) * 16384) +
                               SWZ128((uint32_t)(r * 128 + (c4 & 7) * 16));
                CP_ASYNC16(KS0 + (uint32_t)b * 32768 + off,
                           Kg + (size_t)r * HD + c4 * 4);
            }
            CP_COMMIT();
        }

        // ---- softmax: LDTM c0; wait; LDTM c1 (in flight under ex2 c0)
        uint32_t rr0[32], rr1[32];
        LDTM_X32(rr0, tmSb + cbase);
        TC_WAIT_LD();
        LDTM_X32(rr1, tmSb + cbase + 32);

        if (kt < qt) {          // fast path: no masking
#pragma unroll
            for (int j = 0; j < 32; j++) {
                float e = tf32r(ex2f(__uint_as_float(rr0[j])));
                rr0[j] = __float_as_uint(e);
                lp += e;
            }
        } else {                // diag tile: causal mask
#pragma unroll
            for (int j = 0; j < 32; j++) {
                float e = ex2f(__uint_as_float(rr0[j]));
                e = (cbase + j > rowl) ? 0.0f : tf32r(e);
                rr0[j] = __float_as_uint(e);
                lp += e;
            }
        }

        // PV(kt-1) done -> P TMEM free
        if (kt > 0) MBAR_WAIT(sbase + 24, (kt - 1) & 1);
        STTM_X32(tmP + laneoff + cbase, rr0);

        TC_WAIT_LD();           // rr1 ready
        if (kt < qt) {
#pragma unroll
            for (int j = 0; j < 32; j++) {
                float e = tf32r(ex2f(__uint_as_float(rr1[j])));
                rr1[j] = __float_as_uint(e);
                lp += e;
            }
        } else {
#pragma unroll
            for (int j = 0; j < 32; j++) {
                float e = ex2f(__uint_as_float(rr1[j]));
                e = (cbase + 32 + j > rowl) ? 0.0f : tf32r(e);
                rr1[j] = __float_as_uint(e);
                lp += e;
            }
        }
        STTM_X32(tmP + laneoff + cbase + 32, rr1);
        TC_WAIT_ST();

        // prefetch V(kt+1) into Vbuf[b^1]
        if (kt + 1 < nt) {
            const float* Vg = Vg0 + (size_t)(kt + 1) * 128;
            const uint32_t vdst = VS0 + (uint32_t)(b ^ 1) * 32768;
#pragma unroll
            for (int i = 0; i < 8; i++) {
                int idx = tid + i * 256;
                int r = idx >> 5, c4 = idx & 31;
                uint32_t off = ((uint32_t)(c4 >> 3) * 8192) +
                               SWZ128((uint32_t)(r * 128 + (c4 & 7) * 16));
                CP_ASYNC16(vdst + off, Vg + (size_t)r * SEQ + c4 * 4);
            }
            CP_COMMIT();
        }

        TC_FENCE_BEFORE();
        if (kt + 1 < nt) CP_WAIT(1);
        else CP_WAIT(0);
        __syncthreads();

        if (wid == 0 && elect_one()) {
            FENCE_ASYNC();
            uint64_t vd = MK_DESC(VS0 + (uint32_t)b * 32768);
#pragma unroll
            for (int ks = 0; ks < 16; ks++)
                mma_tf32_ts(tmO, tmP + ks * 8,
                            vd + (ks >> 2) * 512 + (ks & 3) * 2,
                            IDESC_N64, (kt > 0) || (ks > 0));
            TC_COMMIT(sbase + 24);
        }
    }

    // ---- epilogue: combine l, read O, blocked store into g_AO
    lsum[g * 128 + rowl] = lp;
    MBAR_WAIT(sbase + 24, (nt - 1) & 1);
    TC_FENCE_AFTER();
    __syncthreads();
    float l = lsum[rowl] + lsum[128 + rowl];
    {
        uint32_t rr[32];
        LDTM_X32(rr, tmO + g * 32);
        TC_WAIT_LD();
        float inv = 1.0f / l;
        char* dstb = (char*)Og + ((size_t)qt * 32 + h * 2 + g) * 16384;
#pragma unroll
        for (int j4 = 0; j4 < 8; j4++) {
            float4 v = make_float4(
                tf32r(__uint_as_float(rr[j4*4+0]) * inv),
                tf32r(__uint_as_float(rr[j4*4+1]) * inv),
                tf32r(__uint_as_float(rr[j4*4+2]) * inv),
                tf32r(__uint_as_float(rr[j4*4+3]) * inv));
            *(float4*)(dstb + SWZ128((uint32_t)(rowl * 128 + j4 * 16))) = v;
        }
    }
    __syncthreads();
    if (tid == 0) {
        MBAR_INVAL(sbase + 8); MBAR_INVAL(sbase + 16); MBAR_INVAL(sbase + 24);
    }
    __syncthreads();
    if (wid == 0) TC_DEALLOC(tmem, 512);
#else
    const int qt = (int)gridDim.x - 1 - (int)blockIdx.x;
    const int h = blockIdx.y;
    const int tid = threadIdx.x;
    for (int r = tid; r < 128; r += 256) {
        int row = qt * 128 + r;
        const float* q = Q + ((size_t)h * SEQ + row) * HD;
        float l = 0.0f, o[HD];
        for (int d = 0; d < HD; d++) o[d] = 0.0f;
        for (int key = 0; key <= row; key++) {
            const float* kp = K + ((size_t)h * SEQ + key) * HD;
            float s = 0.0f;
            for (int d = 0; d < HD; d++) s += q[d] * kp[d];
            float p = exp2f(s);
            l += p;
            for (int d = 0; d < HD; d++)
                o[d] += p * Vt[(size_t)(h * HD + d) * SEQ + key];
        }
        for (int d = 0; d < HD; d++) {
            int c = h * HD + d;
            *(float*)((char*)Og + blk_off(row, c)) = tf32r(o[d] / l);
        }
    }
#endif
}

// ---------------------------------------------------------------------------
extern "C" void kernel_launch(void* const* d_in, const int* in_sizes, int n_in,
                              void* d_out, int out_size)
{
    (void)in_sizes; (void)n_in; (void)out_size;
    const float* x  = (const float*)d_in[0];
    const float* Wq = (const float*)d_in[1];
    const float* bq = (const float*)d_in[2];
    const float* Wk = (const float*)d_in[3];
    const float* bk = (const float*)d_in[4];
    const float* Wv = (const float*)d_in[5];
    const float* bv = (const float*)d_in[6];
    const float* Wo = (const float*)d_in[7];
    const float* bo = (const float*)d_in[8];
    float* out = (float*)d_out;

    float *Qp, *Kp, *Vp, *AOp, *cosT, *sinT, *xt, *Wt;
    cudaGetSymbolAddress((void**)&Qp, g_Q);
    cudaGetSymbolAddress((void**)&Kp, g_K);
    cudaGetSymbolAddress((void**)&Vp, g_V);
    cudaGetSymbolAddress((void**)&AOp, g_AO);
    cudaGetSymbolAddress((void**)&cosT, g_cosT);
    cudaGetSymbolAddress((void**)&sinT, g_sinT);
    cudaGetSymbolAddress((void**)&xt, g_xt);
    cudaGetSymbolAddress((void**)&Wt, g_Wt);

    cudaFuncSetAttribute(gemm_tc, cudaFuncAttributeMaxDynamicSharedMemorySize,
                         GEMM_SMEM);
    cudaFuncSetAttribute(attn_tc, cudaFuncAttributeMaxDynamicSharedMemorySize,
                         ATTN_SMEM);

    init_invf<<<1, 32>>>();
    init_tables<<<(32 * SEQ) / 256, 256>>>();
    precvt_all<<<8192, 256>>>(x, Wq, Wk, Wv, Wo, xt, Wt);

    dim3 gg(DM / 128, SEQ / 128);   // (8, 32) = 256 CTAs, 2/SM, one wave
    gemm_tc<<<gg, 256, GEMM_SMEM>>>(xt, Wt + 0 * DM * DM, bq, Qp, 27, QSCALE, cosT, sinT);
    gemm_tc<<<gg, 256, GEMM_SMEM>>>(xt, Wt + 1 * DM * DM, bk, Kp, 11, 1.0f, cosT, sinT);
    gemm_tc<<<gg, 256, GEMM_SMEM>>>(xt, Wt + 2 * DM * DM, bv, Vp, 12, 1.0f, cosT, sinT);

    attn_tc<<<dim3(SEQ / 128, NH), 256, ATTN_SMEM>>>(Qp, Kp, Vp, AOp);

    gemm_tc<<<gg, 256, GEMM_SMEM>>>(AOp, Wt + 3 * DM * DM, bo, out, 0, 1.0f, cosT, sinT);
}

// round 14
// speedup vs baseline: 1.0445x; 1.0445x over previous
#include <cuda_runtime.h>
#include <math.h>
#include <cstdint>

#define SEQ 4096
#define DM  1024
#define NH  16
#define HD  64

#if !defined(__CUDA_ARCH__) || defined(__CUDA_ARCH_FEAT_SM103_ALL) || \
    defined(__CUDA_ARCH_FEAT_SM100_ALL) || defined(__CUDA_ARCH_FEAT_SM101_ALL)
#define TC_OK 1
#else
#define TC_OK 0
#endif

// ---------------- scratch ---------------------------------------------------
// xt, Wt, AO live in BLOCKED layout: tile (rb, kc) = rows rb*128..+127,
// cols kc*32..+31, contiguous 16KB with SW128 swizzle pre-applied.
__device__ float g_Q[SEQ * DM];        // [h][s][hd], tf32-rounded, *0.125*log2e
__device__ float g_K[SEQ * DM];        // [h][s][hd], tf32-rounded
__device__ float g_V[SEQ * DM];        // V^T per head [h][d][s], tf32-rounded
__device__ float g_AO[SEQ * DM];       // attention out, BLOCKED, tf32-rounded
__device__ float g_xt[SEQ * DM];       // x, BLOCKED, tf32-rounded
__device__ float g_Wt[4 * DM * DM];    // weights, BLOCKED, tf32-rounded
__device__ float g_invf[32];
__device__ float g_cosT[32 * SEQ];
__device__ float g_sinT[32 * SEQ];

// ---------------- PTX helpers ----------------------------------------------
__device__ __forceinline__ uint32_t smem_u32(const void* p) {
    uint32_t a;
    asm("{ .reg .u64 t; cvta.to.shared.u64 t, %1; cvt.u32.u64 %0, t; }"
        : "=r"(a) : "l"(p));
    return a;
}
__device__ __forceinline__ uint32_t elect_one() {
    uint32_t pred;
    asm volatile("{\n\t.reg .pred p;\n\telect.sync _|p, 0xFFFFFFFF;\n\t"
                 "selp.b32 %0, 1, 0, p;\n\t}" : "=r"(pred));
    return pred;
}
#define TC_ALLOC(smem_addr, n) \
    asm volatile("tcgen05.alloc.cta_group::1.sync.aligned.shared::cta.b32 [%0], %1;" \
                 :: "r"(smem_addr), "r"(n) : "memory")
#define TC_DEALLOC(tmem, n) \
    asm volatile("tcgen05.dealloc.cta_group::1.sync.aligned.b32 %0, %1;" :: "r"(tmem), "r"(n))
#define TC_RELINQ() \
    asm volatile("tcgen05.relinquish_alloc_permit.cta_group::1.sync.aligned;")
#define TC_COMMIT(mbar) \
    asm volatile("tcgen05.commit.cta_group::1.mbarrier::arrive::one.shared::cluster.b64 [%0];" \
                 :: "r"(mbar) : "memory")
#define TC_FENCE_AFTER()  asm volatile("tcgen05.fence::after_thread_sync;" ::: "memory")
#define TC_FENCE_BEFORE() asm volatile("tcgen05.fence::before_thread_sync;" ::: "memory")
#define TC_WAIT_LD()      asm volatile("tcgen05.wait::ld.sync.aligned;" ::: "memory")
#define TC_WAIT_ST()      asm volatile("tcgen05.wait::st.sync.aligned;" ::: "memory")
#define FENCE_ASYNC()     asm volatile("fence.proxy.async.shared::cta;" ::: "memory")
#define MBAR_INIT(a, c) \
    asm volatile("mbarrier.init.shared.b64 [%0], %1;" :: "r"(a), "r"(c) : "memory")
#define MBAR_INVAL(a) \
    asm volatile("mbarrier.inval.shared.b64 [%0];" :: "r"(a) : "memory")
#define MBAR_WAIT(addr, ph) do {                                              \
    uint32_t _m = (addr), _p = (ph), _d;                                      \
    asm volatile("{\n\t.reg .pred p;\n\t"                                     \
        "mbarrier.try_wait.parity.acquire.cta.shared::cta.b64 p, [%1], %2;\n\t" \
        "selp.b32 %0, 1, 0, p;\n\t}" : "=r"(_d) : "r"(_m), "r"(_p) : "memory"); \
    if (!_d) {                                                                \
        asm volatile("{\n\t.reg .pred P1;\n\tWL_%=: \n\t"                     \
            "mbarrier.try_wait.parity.acquire.cta.shared::cta.b64 P1, [%0], %1, 0x989680;\n\t" \
            "@P1 bra.uni WD_%=;\n\tbra.uni WL_%=;\n\tWD_%=:\n\t}"             \
            :: "r"(_m), "r"(_p) : "memory");                                  \
    }                                                                         \
} while (0)
#define LDTM_X32(r, tmem_addr) \
    asm volatile("tcgen05.ld.sync.aligned.32x32b.x32.b32 " \
        "{%0, %1, %2, %3, %4, %5, %6, %7, %8, %9, %10, %11, %12, %13, %14, %15, " \
        "%16, %17, %18, %19, %20, %21, %22, %23, %24, %25, %26, %27, %28, %29, %30, %31}, [%32];" \
        : "=r"((r)[0]),  "=r"((r)[1]),  "=r"((r)[2]),  "=r"((r)[3]),  \
          "=r"((r)[4]),  "=r"((r)[5]),  "=r"((r)[6]),  "=r"((r)[7]),  \
          "=r"((r)[8]),  "=r"((r)[9]),  "=r"((r)[10]), "=r"((r)[11]), \
          "=r"((r)[12]), "=r"((r)[13]), "=r"((r)[14]), "=r"((r)[15]), \
          "=r"((r)[16]), "=r"((r)[17]), "=r"((r)[18]), "=r"((r)[19]), \
          "=r"((r)[20]), "=r"((r)[21]), "=r"((r)[22]), "=r"((r)[23]), \
          "=r"((r)[24]), "=r"((r)[25]), "=r"((r)[26]), "=r"((r)[27]), \
          "=r"((r)[28]), "=r"((r)[29]), "=r"((r)[30]), "=r"((r)[31]) \
        : "r"(tmem_addr))
#define STTM_X32(tmem_addr, r) \
    asm volatile("tcgen05.st.sync.aligned.32x32b.x32.b32 [%0], " \
        "{%1, %2, %3, %4, %5, %6, %7, %8, %9, %10, %11, %12, %13, %14, %15, %16, " \
        "%17, %18, %19, %20, %21, %22, %23, %24, %25, %26, %27, %28, %29, %30, %31, %32};" \
        :: "r"(tmem_addr), \
           "r"((r)[0]),  "r"((r)[1]),  "r"((r)[2]),  "r"((r)[3]),  \
           "r"((r)[4]),  "r"((r)[5]),  "r"((r)[6]),  "r"((r)[7]),  \
           "r"((r)[8]),  "r"((r)[9]),  "r"((r)[10]), "r"((r)[11]), \
           "r"((r)[12]), "r"((r)[13]), "r"((r)[14]), "r"((r)[15]), \
           "r"((r)[16]), "r"((r)[17]), "r"((r)[18]), "r"((r)[19]), \
           "r"((r)[20]), "r"((r)[21]), "r"((r)[22]), "r"((r)[23]), \
           "r"((r)[24]), "r"((r)[25]), "r"((r)[26]), "r"((r)[27]), \
           "r"((r)[28]), "r"((r)[29]), "r"((r)[30]), "r"((r)[31]) \
        : "memory")
#define CP_ASYNC16(smem, gptr) \
    asm volatile("cp.async.cg.shared.global [%0], [%1], 16;" \
                 :: "r"(smem), "l"(gptr) : "memory")
#define CP_COMMIT() asm volatile("cp.async.commit_group;" ::: "memory")
#define CP_WAIT(n)  asm volatile("cp.async.wait_group %0;" :: "n"(n) : "memory")

static constexpr uint64_t DESC_BASE_SW128 =
    (uint64_t(2) << 61) | (uint64_t(1) << 46) | (uint64_t(64) << 32) | (uint64_t(1) << 16);
#define MK_DESC(addr) (DESC_BASE_SW128 | ((uint64_t)((addr) >> 4) & 0x3FFF))
#define SWZ128(off) ((off) ^ (((off) >> 3) & 0x70))

#if TC_OK
__device__ __forceinline__ void mma_tf32_ss(uint32_t d, uint64_t ad, uint64_t bd,
                                            uint32_t idesc, uint32_t en) {
    asm volatile("{\n\t.reg .pred p;\n\tsetp.ne.u32 p, %5, 0;\n\t"
        "tcgen05.mma.cta_group::1.kind::tf32 [%0], %1, %2, %3, {%4, %4, %4, %4}, p;\n\t}"
        :: "r"(d), "l"(ad), "l"(bd), "r"(idesc), "r"(0u), "r"(en) : "memory");
}
__device__ __forceinline__ void mma_tf32_ts(uint32_t d, uint32_t a_tmem, uint64_t bd,
                                            uint32_t idesc, uint32_t en) {
    asm volatile("{\n\t.reg .pred p;\n\tsetp.ne.u32 p, %5, 0;\n\t"
        "tcgen05.mma.cta_group::1.kind::tf32 [%0], [%1], %2, %3, {%4, %4, %4, %4}, p;\n\t}"
        :: "r"(d), "r"(a_tmem), "l"(bd), "r"(idesc), "r"(0u), "r"(en) : "memory");
}
#endif

__device__ __forceinline__ float tf32r(float x) {
    uint32_t u;
    asm("cvt.rna.tf32.f32 %0, %1;" : "=r"(u) : "f"(x));
    return __uint_as_float(u);
}
__device__ __forceinline__ float ex2f(float x) {
    float y;
    asm("ex2.approx.f32 %0, %1;" : "=f"(y) : "f"(x));
    return y;
}

static constexpr uint32_t IDESC_N128 =
    (1u << 4) | (2u << 7) | (2u << 10) | (16u << 17) | (8u << 24);
static constexpr uint32_t IDESC_N64 =
    (1u << 4) | (2u << 7) | (2u << 10) | (8u << 17) | (8u << 24);

// (1/sqrt(64)) * log2(e)
#define QSCALE 0.18033688011112042f

__host__ __device__ __forceinline__ uint32_t blk_off(int r, int c) {
    return ((uint32_t)(r >> 7) * 32 + (uint32_t)(c >> 5)) * 16384u +
           SWZ128((uint32_t)((r & 127) << 7) + (uint32_t)((c & 31) << 2));
}

// ---------------- init / precvt ---------------------------------------------
__global__ void init_invf() {
    int j = threadIdx.x;
    double e = (double)(2 * j) / 64.0;
    g_invf[j] = (float)(1.0 / pow(10000.0, e));
}
__global__ __launch_bounds__(256) void init_tables() {
    int idx = blockIdx.x * blockDim.x + threadIdx.x;
    int j = idx >> 12;
    int s = idx & (SEQ - 1);
    float ang = (float)s * g_invf[j];
    float sn, cs;
    sincosf(ang, &sn, &cs);
    g_cosT[idx] = cs;
    g_sinT[idx] = sn;
}
__global__ __launch_bounds__(256) void precvt_all(
    const float* __restrict__ x,
    const float* __restrict__ Wq, const float* __restrict__ Wk,
    const float* __restrict__ Wv, const float* __restrict__ Wo,
    float* __restrict__ xt, float* __restrict__ Wt)
{
    int i = blockIdx.x * 256 + threadIdx.x;
    const float4* src;
    char* dstbase;
    int off;
    if (i < (1 << 20)) {
        src = (const float4*)x; dstbase = (char*)xt; off = i;
    } else {
        int k = i - (1 << 20);
        int w = k >> 18;
        off = k & ((1 << 18) - 1);
        src = (const float4*)(w == 0 ? Wq : w == 1 ? Wk : w == 2 ? Wv : Wo);
        dstbase = (char*)(Wt + (size_t)w * DM * DM);
    }
    float4 v = src[off];
    v.x = tf32r(v.x); v.y = tf32r(v.y); v.z = tf32r(v.z); v.w = tf32r(v.w);
    int r = off >> 8;
    int c4 = off & 255;
    uint32_t byte = ((uint32_t)(r >> 7) * 32 + (uint32_t)(c4 >> 3)) * 16384u +
                    SWZ128((uint32_t)((r & 127) << 7) + (uint32_t)((c4 & 7) << 4));
    *(float4*)(dstbase + byte) = v;
}

// ---------------------------------------------------------------------------
// Fused Q+K projection GEMM: shares the x chunk across two weight operands.
// 48KB/stage (x + Wq + Wk), 2 stages = 96KB -> 2 CTAs/SM, 256 CTAs one wave.
// Two TMEM accumulators (tmQ @0, tmK @128); one commit per stage covers both.
// Epilogue: bias + RoPE + (QSCALE for Q) + tf32 round, store [h][s][hd].
// ---------------------------------------------------------------------------
#define QK_SMEM 99840

__global__ __launch_bounds__(256, 2) void gemm_qk(
    const float* __restrict__ A, const float* __restrict__ Bq,
    const float* __restrict__ Bk,
    const float* __restrict__ biasq, const float* __restrict__ biask,
    float* __restrict__ Cq, float* __restrict__ Ck,
    const float* __restrict__ cosT, const float* __restrict__ sinT)
{
#if TC_OK
    extern __shared__ char sm[];
    const uint32_t sbase = smem_u32(sm);
    const uint32_t tile0 = (sbase + 64 + 1023) & ~1023u;

    const int tid = threadIdx.x;
    const int wid = tid >> 5;
    const int row0 = blockIdx.y << 7;
    const int col0 = blockIdx.x << 7;

    if (wid == 0) TC_ALLOC(sbase, 256);
    if (tid == 0) { MBAR_INIT(sbase + 8, 1); MBAR_INIT(sbase + 16, 1); }
    __syncthreads();
    uint32_t tmem;
    asm volatile("ld.shared.b32 %0, [%1];" : "=r"(tmem) : "r"(sbase));
    if (wid == 0) TC_RELINQ();
    const uint32_t tmQ = tmem;
    const uint32_t tmK = tmem + 128;

    const char* Asrc  = (const char*)A  + (size_t)(row0 >> 7) * 32 * 16384;
    const char* Bqsrc = (const char*)Bq + (size_t)(col0 >> 7) * 32 * 16384;
    const char* Bksrc = (const char*)Bk + (size_t)(col0 >> 7) * 32 * 16384;

    for (int kc = 0; kc < 33; kc++) {
        if (kc < 32) {
            const int s = kc & 1;
            if (kc >= 2) MBAR_WAIT(sbase + 8 + s * 8, ((kc - 2) / 2) & 1);
            const uint32_t sb = tile0 + s * 49152;
            const char* Ag  = Asrc  + (size_t)kc * 16384;
            const char* Bqg = Bqsrc + (size_t)kc * 16384;
            const char* Bkg = Bksrc + (size_t)kc * 16384;
#pragma unroll
            for (int t = 0; t < 4; t++) {
                uint32_t off = (uint32_t)tid * 16 + t * 4096;
                CP_ASYNC16(sb + off, Ag + off);
                CP_ASYNC16(sb + 16384 + off, Bqg + off);
                CP_ASYNC16(sb + 32768 + off, Bkg + off);
            }
            CP_COMMIT();
        }
        if (kc >= 1) {
            const int j = kc - 1;
            const int sj = j & 1;
            if (kc < 32) CP_WAIT(1);
            else CP_WAIT(0);
            __syncthreads();
            if (wid == 0 && elect_one()) {
                FENCE_ASYNC();
                uint64_t ad  = MK_DESC(tile0 + sj * 49152);
                uint64_t bdq = MK_DESC(tile0 + sj * 49152 + 16384);
                uint64_t bdk = MK_DESC(tile0 + sj * 49152 + 32768);
#pragma unroll
                for (int ks = 0; ks < 4; ks++)
                    mma_tf32_ss(tmQ, ad + ks * 2, bdq + ks * 2, IDESC_N128,
                                (j > 0) || (ks > 0));
#pragma unroll
                for (int ks = 0; ks < 4; ks++)
                    mma_tf32_ss(tmK, ad + ks * 2, bdk + ks * 2, IDESC_N128,
                                (j > 0) || (ks > 0));
                TC_COMMIT(sbase + 8 + sj * 8);
            }
        }
    }
    // drain: done0 fired 16x (j=0..30 even), done1 16x (j=1..31 odd);
    // last in-loop wait consumed phase 14 -> final parity 1 unambiguous,
    // all threads tracked every phase (R13 pattern).
    MBAR_WAIT(sbase + 8, 1);
    MBAR_WAIT(sbase + 16, 1);
    TC_FENCE_AFTER();

    if (tid < 128) {
        const int lid = tid & 31;
        const int w = tid >> 5;
        const int row = row0 + w * 32 + lid;
#pragma unroll
        for (int m = 0; m < 2; m++) {
            const uint32_t tm = m ? tmK : tmQ;
            const float* bias = m ? biask : biasq;
            float* C = m ? Ck : Cq;
            const float sc = m ? 1.0f : QSCALE;
#pragma unroll
            for (int half = 0; half < 2; half++) {
                uint32_t rr[64];
                LDTM_X32(rr, tm + half * 64);
                LDTM_X32(rr + 32, tm + half * 64 + 32);
                TC_WAIT_LD();
                const int gc0 = col0 + half * 64;
                float v[64];
#pragma unroll
                for (int j = 0; j < 64; j++)
                    v[j] = __uint_as_float(rr[j]) + __ldg(&bias[gc0 + j]);
#pragma unroll
                for (int j = 0; j < 32; j++) {
                    float cs = __ldg(&cosT[j * SEQ + row]);
                    float sn = __ldg(&sinT[j * SEQ + row]);
                    float a = v[j], b2 = v[j + 32];
                    v[j]      = a * cs - b2 * sn;
                    v[j + 32] = b2 * cs + a * sn;
                }
#pragma unroll
                for (int j = 0; j < 64; j++) v[j] = tf32r(v[j] * sc);
                int hh = gc0 >> 6;
                float* dst = C + ((size_t)hh * SEQ + row) * HD;
#pragma unroll
                for (int j4 = 0; j4 < 64; j4 += 4)
                    *(float4*)(dst + j4) = make_float4(v[j4], v[j4+1], v[j4+2], v[j4+3]);
            }
        }
    }
    __syncthreads();
    if (tid == 0) { MBAR_INVAL(sbase + 8); MBAR_INVAL(sbase + 16); }
    __syncthreads();
    if (wid == 0) TC_DEALLOC(tmem, 256);
#else
    // Fallback (never executed on GB300).
    const int tid = threadIdx.x;
    const int row0 = blockIdx.y << 7;
    const int col0 = blockIdx.x << 7;
    for (int e = tid; e < 128 * 128; e += 256) {
        int r = row0 + (e >> 7);
        int c = col0 + (e & 127);
        for (int m = 0; m < 2; m++) {
            const float* B = m ? Bk : Bq;
            const float* bias = m ? biask : biasq;
            float* C = m ? Ck : Cq;
            float sc = m ? 1.0f : QSCALE;
            int j = c & 63;
            int jp = (j < 32) ? j + 32 : j - 32;
            int cp = (c & ~63) | jp;
            float acc = bias[c], acc2 = bias[cp];
            for (int k = 0; k < DM; k++) {
                float av = *(const float*)((const char*)A + blk_off(r, k));
                acc  += av * *(const float*)((const char*)B + blk_off(c, k));
                acc2 += av * *(const float*)((const char*)B + blk_off(cp, k));
            }
            int f = (j < 32) ? j : j - 32;
            float cs = cosT[f * SEQ + r], sn = sinT[f * SEQ + r];
            float outv = (j < 32) ? (acc * cs - acc2 * sn) : (acc * cs + acc2 * sn);
            C[(((size_t)(c >> 6) * SEQ + r) * HD) + (c & 63)] = tf32r(outv * sc);
        }
    }
#endif
}

// ---------------------------------------------------------------------------
// tcgen05 tf32 GEMM (V projection + output proj), R13-proven.
// mode: bit0 head layout; bit1 RoPE; bit2 V^T; bit3 tf32-round; bit4 scale.
// ---------------------------------------------------------------------------
#define GEMM_SMEM 100352

__global__ __launch_bounds__(256, 2) void gemm_tc(
    const float* __restrict__ A, const float* __restrict__ B,
    const float* __restrict__ bias, float* __restrict__ C, int mode, float sc,
    const float* __restrict__ cosT, const float* __restrict__ sinT)
{
#if TC_OK
    extern __shared__ char sm[];
    const uint32_t sbase = smem_u32(sm);
    const uint32_t tile0 = (sbase + 64 + 1023) & ~1023u;

    const int tid = threadIdx.x;
    const int wid = tid >> 5;
    const int row0 = blockIdx.y << 7;
    const int col0 = blockIdx.x << 7;

    if (wid == 0) TC_ALLOC(sbase, 128);
    if (tid == 0) {
        MBAR_INIT(sbase + 8, 1);  MBAR_INIT(sbase + 16, 1);
        MBAR_INIT(sbase + 24, 1);
    }
    __syncthreads();
    uint32_t tmem;
    asm volatile("ld.shared.b32 %0, [%1];" : "=r"(tmem) : "r"(sbase));
    if (wid == 0) TC_RELINQ();

    const char* Asrc = (const char*)A + (size_t)(row0 >> 7) * 32 * 16384;
    const char* Bsrc = (const char*)B + (size_t)(col0 >> 7) * 32 * 16384;

    for (int kc = 0; kc < 34; kc++) {
        if (kc < 32) {
            const int s = kc % 3;
            if (kc >= 3) MBAR_WAIT(sbase + 8 + s * 8, ((kc - 3) / 3) & 1);
            const uint32_t sA = tile0 + s * 32768;
            const char* Ag = Asrc + (size_t)kc * 16384;
            const char* Bg = Bsrc + (size_t)kc * 16384;
#pragma unroll
            for (int t = 0; t < 4; t++) {
                uint32_t off = (uint32_t)tid * 16 + t * 4096;
                CP_ASYNC16(sA + off, Ag + off);
                CP_ASYNC16(sA + 16384 + off, Bg + off);
            }
            CP_COMMIT();
        }
        if (kc >= 2) {
            const int j = kc - 2;
            const int sj = j % 3;
            if (kc < 32) CP_WAIT(2);
            else if (kc == 32) CP_WAIT(1);
            else CP_WAIT(0);
            __syncthreads();
            if (wid == 0 && elect_one()) {
                FENCE_ASYNC();
                uint64_t ad = MK_DESC(tile0 + sj * 32768);
                uint64_t bd = MK_DESC(tile0 + sj * 32768 + 16384);
#pragma unroll
                for (int ks = 0; ks < 4; ks++)
                    mma_tf32_ss(tmem, ad + ks * 2, bd + ks * 2, IDESC_N128,
                                (j > 0) || (ks > 0));
                TC_COMMIT(sbase + 8 + sj * 8);
            }
        }
    }
    MBAR_WAIT(sbase + 8, 0);
    MBAR_WAIT(sbase + 16, 0);
    MBAR_WAIT(sbase + 24, 1);
    TC_FENCE_AFTER();

    if (tid < 128) {
        const int lid = tid & 31;
        const int w = tid >> 5;
        const int row = row0 + w * 32 + lid;
        const bool rope = (mode & 2) != 0;
        const bool rnd  = (mode & 8) != 0;
        const bool scl  = (mode & 16) != 0;
#pragma unroll
        for (int half = 0; half < 2; half++) {
            uint32_t rr[64];
            LDTM_X32(rr, tmem + half * 64);
            LDTM_X32(rr + 32, tmem + half * 64 + 32);
            TC_WAIT_LD();
            const int gc0 = col0 + half * 64;
            float v[64];
#pragma unroll
            for (int j = 0; j < 64; j++)
                v[j] = __uint_as_float(rr[j]) + __ldg(&bias[gc0 + j]);
            if (rope) {
#pragma unroll
                for (int j = 0; j < 32; j++) {
                    float cs = __ldg(&cosT[j * SEQ + row]);
                    float sn = __ldg(&sinT[j * SEQ + row]);
                    float a = v[j], b2 = v[j + 32];
                    v[j]      = a * cs - b2 * sn;
                    v[j + 32] = b2 * cs + a * sn;
                }
            }
            if (scl) {
#pragma unroll
                for (int j = 0; j < 64; j++) v[j] *= sc;
            }
            if (rnd) {
#pragma unroll
                for (int j = 0; j < 64; j++) v[j] = tf32r(v[j]);
            }
            if (mode & 4) {
                int hh = gc0 >> 6;
                float* dst = C + (size_t)(hh * HD) * SEQ + row;
#pragma unroll
                for (int j = 0; j < 64; j++)
                    dst[(size_t)j * SEQ] = v[j];
            } else if (mode & 1) {
                int hh = gc0 >> 6;
                float* dst = C + ((size_t)hh * SEQ + row) * HD;
#pragma unroll
                for (int j4 = 0; j4 < 64; j4 += 4)
                    *(float4*)(dst + j4) = make_float4(v[j4], v[j4+1], v[j4+2], v[j4+3]);
            } else {
                float* dst = C + (size_t)row * DM + gc0;
#pragma unroll
                for (int j4 = 0; j4 < 64; j4 += 4)
                    *(float4*)(dst + j4) = make_float4(v[j4], v[j4+1], v[j4+2], v[j4+3]);
            }
        }
    }
    __syncthreads();
    if (tid == 0) {
        MBAR_INVAL(sbase + 8);  MBAR_INVAL(sbase + 16);
        MBAR_INVAL(sbase + 24);
    }
    __syncthreads();
    if (wid == 0) TC_DEALLOC(tmem, 128);
#else
    const int tid = threadIdx.x;
    const int row0 = blockIdx.y << 7;
    const int col0 = blockIdx.x << 7;
    for (int e = tid; e < 128 * 128; e += 256) {
        int r = row0 + (e >> 7);
        int c = col0 + (e & 127);
        float acc = bias[c];
        for (int k = 0; k < DM; k++)
            acc += *(const float*)((const char*)A + blk_off(r, k)) *
                   *(const float*)((const char*)B + blk_off(c, k));
        float outv = acc;
        if (mode & 2) {
            int j = c & 63;
            int jp = (j < 32) ? j + 32 : j - 32;
            int cp = (c & ~63) | jp;
            float acc2 = bias[cp];
            for (int k = 0; k < DM; k++)
                acc2 += *(const float*)((const char*)A + blk_off(r, k)) *
                        *(const float*)((const char*)B + blk_off(cp, k));
            int f = (j < 32) ? j : j - 32;
            float cs = cosT[f * SEQ + r], sn = sinT[f * SEQ + r];
            outv = (j < 32) ? (acc * cs - acc2 * sn) : (acc * cs + acc2 * sn);
        }
        if (mode & 16) outv *= sc;
        if (mode & 8)  outv = tf32r(outv);
        if (mode & 4)      C[(size_t)((c >> 6) * HD + (c & 63)) * SEQ + r] = outv;
        else if (mode & 1) C[(((size_t)(c >> 6) * SEQ + r) * HD) + (c & 63)] = outv;
        else               C[(size_t)r * DM + c] = outv;
    }
#endif
}

// ---------------------------------------------------------------------------
// tcgen05 flash attention (tf32), causal — PROVEN R13 version, unchanged.
// TMEM: S0 @0 | S1 @128 | O @256 | P @320.
// ---------------------------------------------------------------------------
#if TC_OK
#define ATTN_SMEM 166912
#else
#define ATTN_SMEM 0
#endif

__global__ __launch_bounds__(256) void attn_tc(
    const float* __restrict__ Q, const float* __restrict__ K,
    const float* __restrict__ Vt, float* __restrict__ Og)
{
#if TC_OK
    extern __shared__ char sm[];
    const uint32_t sbase = smem_u32(sm);
    float* lsum = (float*)(sm + 64);                 // [2][128]
    const uint32_t tile0 = (sbase + 1088 + 1023) & ~1023u;
    const uint32_t QS  = tile0;
    const uint32_t KS0 = tile0 + 32768;
    const uint32_t VS0 = tile0 + 98304;

    const int qt = (int)gridDim.x - 1 - (int)blockIdx.x;
    const int h  = blockIdx.y;
    const int nt = qt + 1;
    const int tid = threadIdx.x;
    const int wid = tid >> 5;
    const int lane = tid & 31;
    const int g = wid >> 2;
    const int rowl = ((wid & 3) << 5) + lane;
    const int cbase = g << 6;
    const uint32_t laneoff = ((uint32_t)(wid & 3)) << 21;

    if (wid == 0) TC_ALLOC(sbase, 512);
    if (tid == 0) {
        MBAR_INIT(sbase + 8, 1);
        MBAR_INIT(sbase + 16, 1);
        MBAR_INIT(sbase + 24, 1);
    }
    __syncthreads();
    uint32_t tmem;
    asm volatile("ld.shared.b32 %0, [%1];" : "=r"(tmem) : "r"(sbase));
    if (wid == 0) TC_RELINQ();
    const uint32_t tmO = tmem + 256;
    const uint32_t tmP = tmem + 320;

    const float* Qg  = Q + ((size_t)h * SEQ + (size_t)qt * 128) * HD;
    const float* Kg0 = K + (size_t)h * SEQ * HD;
    const float* Vg0 = Vt + (size_t)(h * HD) * SEQ;
    const uint64_t adQ = MK_DESC(QS);

    // ---- prologue: Q, K(0), V(0); K(1)
#pragma unroll
    for (int i = 0; i < 8; i++) {
        int idx = tid + i * 256;
        int r = idx >> 4, c4 = idx & 15;
        uint32_t off = ((uint32_t)(c4 >> 3) * 16384) +
                       SWZ128((uint32_t)(r * 128 + (c4 & 7) * 16));
        CP_ASYNC16(QS + off, Qg + (size_t)r * HD + c4 * 4);
        CP_ASYNC16(KS0 + off, Kg0 + (size_t)r * HD + c4 * 4);
    }
#pragma unroll
    for (int i = 0; i < 8; i++) {
        int idx = tid + i * 256;
        int r = idx >> 5, c4 = idx & 31;
        uint32_t off = ((uint32_t)(c4 >> 3) * 8192) +
                       SWZ128((uint32_t)(r * 128 + (c4 & 7) * 16));
        CP_ASYNC16(VS0 + off, Vg0 + (size_t)r * SEQ + c4 * 4);
    }
    CP_COMMIT();
    if (nt > 1) {
        const float* Kg = Kg0 + (size_t)128 * HD;
#pragma unroll
        for (int i = 0; i < 8; i++) {
            int idx = tid + i * 256;
            int r = idx >> 4, c4 = idx & 15;
            uint32_t off = ((uint32_t)(c4 >> 3) * 16384) +
                           SWZ128((uint32_t)(r * 128 + (c4 & 7) * 16));
            CP_ASYNC16(KS0 + 32768 + off, Kg + (size_t)r * HD + c4 * 4);
        }
        CP_COMMIT();
    }
    CP_WAIT(0);
    __syncthreads();
    if (wid == 0 && elect_one()) {
        FENCE_ASYNC();
        uint64_t bd = MK_DESC(KS0);
#pragma unroll
        for (int ks = 0; ks < 8; ks++)
            mma_tf32_ss(tmem, adQ + (ks >> 2) * 1024 + (ks & 3) * 2,
                        bd + (ks >> 2) * 1024 + (ks & 3) * 2, IDESC_N128, ks > 0);
        TC_COMMIT(sbase + 8);
    }

    float lp = 0.0f;

    for (int kt = 0; kt < nt; kt++) {
        const int b = kt & 1;
        const uint32_t tmSb = tmem + (uint32_t)b * 128;

        MBAR_WAIT(sbase + 8 + b * 8, (kt >> 1) & 1);   // S(kt) ready
        TC_FENCE_AFTER();

        // issue S(kt+1) now (overlaps softmax below)
        if (kt + 1 < nt && wid == 0 && elect_one()) {
            FENCE_ASYNC();
            uint64_t bd = MK_DESC(KS0 + (uint32_t)(b ^ 1) * 32768);
            uint32_t d = tmem + (uint32_t)(b ^ 1) * 128;
#pragma unroll
            for (int ks = 0; ks < 8; ks++)
                mma_tf32_ss(d, adQ + (ks >> 2) * 1024 + (ks & 3) * 2,
                            bd + (ks >> 2) * 1024 + (ks & 3) * 2,
                            IDESC_N128, ks > 0);
            TC_COMMIT(sbase + 8 + (b ^ 1) * 8);
        }

        // prefetch K(kt+2) into Kbuf[b]
        if (kt + 2 < nt) {
            const float* Kg = Kg0 + (size_t)(kt + 2) * 128 * HD;
#pragma unroll
            for (int i = 0; i < 8; i++) {
                int idx = tid + i * 256;
                int r = idx >> 4, c4 = idx & 15;
                uint32_t off = ((uint32_t)(c4 >> 3) * 16384) +
                               SWZ128((uint32_t)(r * 128 + (c4 & 7) * 16));
                CP_ASYNC16(KS0 + (uint32_t)b * 32768 + off,
                           Kg + (size_t)r * HD + c4 * 4);
            }
            CP_COMMIT();
        }

        // ---- softmax: LDTM c0; wait; LDTM c1 (in flight under ex2 c0)
        uint32_t rr0[32], rr1[32];
        LDTM_X32(rr0, tmSb + cbase);
        TC_WAIT_LD();
        LDTM_X32(rr1, tmSb + cbase + 32);

        if (kt < qt) {          // fast path: no masking
#pragma unroll
            for (int j = 0; j < 32; j++) {
                float e = tf32r(ex2f(__uint_as_float(rr0[j])));
                rr0[j] = __float_as_uint(e);
                lp += e;
            }
        } else {                // diag tile: causal mask
#pragma unroll
            for (int j = 0; j < 32; j++) {
                float e = ex2f(__uint_as_float(rr0[j]));
                e = (cbase + j > rowl) ? 0.0f : tf32r(e);
                rr0[j] = __float_as_uint(e);
                lp += e;
            }
        }

        // PV(kt-1) done -> P TMEM free
        if (kt > 0) MBAR_WAIT(sbase + 24, (kt - 1) & 1);
        STTM_X32(tmP + laneoff + cbase, rr0);

        TC_WAIT_LD();           // rr1 ready
        if (kt < qt) {
#pragma unroll
            for (int j = 0; j < 32; j++) {
                float e = tf32r(ex2f(__uint_as_float(rr1[j])));
                rr1[j] = __float_as_uint(e);
                lp += e;
            }
        } else {
#pragma unroll
            for (int j = 0; j < 32; j++) {
                float e = ex2f(__uint_as_float(rr1[j]));
                e = (cbase + 32 + j > rowl) ? 0.0f : tf32r(e);
                rr1[j] = __float_as_uint(e);
                lp += e;
            }
        }
        STTM_X32(tmP + laneoff + cbase + 32, rr1);
        TC_WAIT_ST();

        // prefetch V(kt+1) into Vbuf[b^1]
        if (kt + 1 < nt) {
            const float* Vg = Vg0 + (size_t)(kt + 1) * 128;
            const uint32_t vdst = VS0 + (uint32_t)(b ^ 1) * 32768;
#pragma unroll
            for (int i = 0; i < 8; i++) {
                int idx = tid + i * 256;
                int r = idx >> 5, c4 = idx & 31;
                uint32_t off = ((uint32_t)(c4 >> 3) * 8192) +
                               SWZ128((uint32_t)(r * 128 + (c4 & 7) * 16));
                CP_ASYNC16(vdst + off, Vg + (size_t)r * SEQ + c4 * 4);
            }
            CP_COMMIT();
        }

        TC_FENCE_BEFORE();
        if (kt + 1 < nt) CP_WAIT(1);
        else CP_WAIT(0);
        __syncthreads();

        if (wid == 0 && elect_one()) {
            FENCE_ASYNC();
            uint64_t vd = MK_DESC(VS0 + (uint32_t)b * 32768);
#pragma unroll
            for (int ks = 0; ks < 16; ks++)
                mma_tf32_ts(tmO, tmP + ks * 8,
                            vd + (ks >> 2) * 512 + (ks & 3) * 2,
                            IDESC_N64, (kt > 0) || (ks > 0));
            TC_COMMIT(sbase + 24);
        }
    }

    // ---- epilogue: combine l, read O, blocked store into g_AO
    lsum[g * 128 + rowl] = lp;
    MBAR_WAIT(sbase + 24, (nt - 1) & 1);
    TC_FENCE_AFTER();
    __syncthreads();
    float l = lsum[rowl] + lsum[128 + rowl];
    {
        uint32_t rr[32];
        LDTM_X32(rr, tmO + g * 32);
        TC_WAIT_LD();
        float inv = 1.0f / l;
        char* dstb = (char*)Og + ((size_t)qt * 32 + h * 2 + g) * 16384;
#pragma unroll
        for (int j4 = 0; j4 < 8; j4++) {
            float4 v = make_float4(
                tf32r(__uint_as_float(rr[j4*4+0]) * inv),
                tf32r(__uint_as_float(rr[j4*4+1]) * inv),
                tf32r(__uint_as_float(rr[j4*4+2]) * inv),
                tf32r(__uint_as_float(rr[j4*4+3]) * inv));
            *(float4*)(dstb + SWZ128((uint32_t)(rowl * 128 + j4 * 16))) = v;
        }
    }
    __syncthreads();
    if (tid == 0) {
        MBAR_INVAL(sbase + 8); MBAR_INVAL(sbase + 16); MBAR_INVAL(sbase + 24);
    }
    __syncthreads();
    if (wid == 0) TC_DEALLOC(tmem, 512);
#else
    const int qt = (int)gridDim.x - 1 - (int)blockIdx.x;
    const int h = blockIdx.y;
    const int tid = threadIdx.x;
    for (int r = tid; r < 128; r += 256) {
        int row = qt * 128 + r;
        const float* q = Q + ((size_t)h * SEQ + row) * HD;
        float l = 0.0f, o[HD];
        for (int d = 0; d < HD; d++) o[d] = 0.0f;
        for (int key = 0; key <= row; key++) {
            const float* kp = K + ((size_t)h * SEQ + key) * HD;
            float s = 0.0f;
            for (int d = 0; d < HD; d++) s += q[d] * kp[d];
            float p = exp2f(s);
            l += p;
            for (int d = 0; d < HD; d++)
                o[d] += p * Vt[(size_t)(h * HD + d) * SEQ + key];
        }
        for (int d = 0; d < HD; d++) {
            int c = h * HD + d;
            *(float*)((char*)Og + blk_off(row, c)) = tf32r(o[d] / l);
        }
    }
#endif
}

// ---------------------------------------------------------------------------
extern "C" void kernel_launch(void* const* d_in, const int* in_sizes, int n_in,
                              void* d_out, int out_size)
{
    (void)in_sizes; (void)n_in; (void)out_size;
    const float* x  = (const float*)d_in[0];
    const float* Wq = (const float*)d_in[1];
    const float* bq = (const float*)d_in[2];
    const float* Wk = (const float*)d_in[3];
    const float* bk = (const float*)d_in[4];
    const float* Wv = (const float*)d_in[5];
    const float* bv = (const float*)d_in[6];
    const float* Wo = (const float*)d_in[7];
    const float* bo = (const float*)d_in[8];
    float* out = (float*)d_out;

    float *Qp, *Kp, *Vp, *AOp, *cosT, *sinT, *xt, *Wt;
    cudaGetSymbolAddress((void**)&Qp, g_Q);
    cudaGetSymbolAddress((void**)&Kp, g_K);
    cudaGetSymbolAddress((void**)&Vp, g_V);
    cudaGetSymbolAddress((void**)&AOp, g_AO);
    cudaGetSymbolAddress((void**)&cosT, g_cosT);
    cudaGetSymbolAddress((void**)&sinT, g_sinT);
    cudaGetSymbolAddress((void**)&xt, g_xt);
    cudaGetSymbolAddress((void**)&Wt, g_Wt);

    cudaFuncSetAttribute(gemm_tc, cudaFuncAttributeMaxDynamicSharedMemorySize,
                         GEMM_SMEM);
    cudaFuncSetAttribute(gemm_qk, cudaFuncAttributeMaxDynamicSharedMemorySize,
                         QK_SMEM);
    cudaFuncSetAttribute(attn_tc, cudaFuncAttributeMaxDynamicSharedMemorySize,
                         ATTN_SMEM);

    init_invf<<<1, 32>>>();
    init_tables<<<(32 * SEQ) / 256, 256>>>();
    precvt_all<<<8192, 256>>>(x, Wq, Wk, Wv, Wo, xt, Wt);

    dim3 gg(DM / 128, SEQ / 128);   // (8, 32) = 256 CTAs, 2/SM, one wave
    gemm_qk<<<gg, 256, QK_SMEM>>>(xt, Wt + 0 * DM * DM, Wt + 1 * DM * DM,
                                  bq, bk, Qp, Kp, cosT, sinT);
    gemm_tc<<<gg, 256, GEMM_SMEM>>>(xt, Wt + 2 * DM * DM, bv, Vp, 12, 1.0f, cosT, sinT);

    attn_tc<<<dim3(SEQ / 128, NH), 256, ATTN_SMEM>>>(Qp, Kp, Vp, AOp);

    gemm_tc<<<gg, 256, GEMM_SMEM>>>(AOp, Wt + 3 * DM * DM, bo, out, 0, 1.0f, cosT, sinT);
}

// round 15
// speedup vs baseline: 1.0601x; 1.0149x over previous
#include <cuda_runtime.h>
#include <math.h>
#include <cstdint>

#define SEQ 4096
#define DM  1024
#define NH  16
#define HD  64

#if !defined(__CUDA_ARCH__) || defined(__CUDA_ARCH_FEAT_SM103_ALL) || \
    defined(__CUDA_ARCH_FEAT_SM100_ALL) || defined(__CUDA_ARCH_FEAT_SM101_ALL)
#define TC_OK 1
#else
#define TC_OK 0
#endif

// ---------------- scratch ---------------------------------------------------
// xt, Wt, AO live in BLOCKED layout: tile (rb, kc) = rows rb*128..+127,
// cols kc*32..+31, contiguous 16KB with SW128 swizzle pre-applied.
__device__ float g_Q[SEQ * DM];        // [h][s][hd], tf32-rounded, *0.125*log2e
__device__ float g_K[SEQ * DM];        // [h][s][hd], tf32-rounded
__device__ float g_V[SEQ * DM];        // V^T per head [h][d][s], tf32-rounded
__device__ float g_AO[SEQ * DM];       // attention out, BLOCKED, tf32-rounded
__device__ float g_xt[SEQ * DM];       // x, BLOCKED, tf32-rounded
__device__ float g_Wt[4 * DM * DM];    // weights, BLOCKED, tf32-rounded
__device__ float g_invf[32];
__device__ float g_cosT[32 * SEQ];
__device__ float g_sinT[32 * SEQ];

// ---------------- PTX helpers ----------------------------------------------
__device__ __forceinline__ uint32_t smem_u32(const void* p) {
    uint32_t a;
    asm("{ .reg .u64 t; cvta.to.shared.u64 t, %1; cvt.u32.u64 %0, t; }"
        : "=r"(a) : "l"(p));
    return a;
}
__device__ __forceinline__ uint32_t elect_one() {
    uint32_t pred;
    asm volatile("{\n\t.reg .pred p;\n\telect.sync _|p, 0xFFFFFFFF;\n\t"
                 "selp.b32 %0, 1, 0, p;\n\t}" : "=r"(pred));
    return pred;
}
#define TC_ALLOC(smem_addr, n) \
    asm volatile("tcgen05.alloc.cta_group::1.sync.aligned.shared::cta.b32 [%0], %1;" \
                 :: "r"(smem_addr), "r"(n) : "memory")
#define TC_DEALLOC(tmem, n) \
    asm volatile("tcgen05.dealloc.cta_group::1.sync.aligned.b32 %0, %1;" :: "r"(tmem), "r"(n))
#define TC_RELINQ() \
    asm volatile("tcgen05.relinquish_alloc_permit.cta_group::1.sync.aligned;")
#define TC_COMMIT(mbar) \
    asm volatile("tcgen05.commit.cta_group::1.mbarrier::arrive::one.shared::cluster.b64 [%0];" \
                 :: "r"(mbar) : "memory")
#define TC_FENCE_AFTER()  asm volatile("tcgen05.fence::after_thread_sync;" ::: "memory")
#define TC_FENCE_BEFORE() asm volatile("tcgen05.fence::before_thread_sync;" ::: "memory")
#define TC_WAIT_LD()      asm volatile("tcgen05.wait::ld.sync.aligned;" ::: "memory")
#define TC_WAIT_ST()      asm volatile("tcgen05.wait::st.sync.aligned;" ::: "memory")
#define FENCE_ASYNC()     asm volatile("fence.proxy.async.shared::cta;" ::: "memory")
#define MBAR_INIT(a, c) \
    asm volatile("mbarrier.init.shared.b64 [%0], %1;" :: "r"(a), "r"(c) : "memory")
#define MBAR_INVAL(a) \
    asm volatile("mbarrier.inval.shared.b64 [%0];" :: "r"(a) : "memory")
#define MBAR_WAIT(addr, ph) do {                                              \
    uint32_t _m = (addr), _p = (ph), _d;                                      \
    asm volatile("{\n\t.reg .pred p;\n\t"                                     \
        "mbarrier.try_wait.parity.acquire.cta.shared::cta.b64 p, [%1], %2;\n\t" \
        "selp.b32 %0, 1, 0, p;\n\t}" : "=r"(_d) : "r"(_m), "r"(_p) : "memory"); \
    if (!_d) {                                                                \
        asm volatile("{\n\t.reg .pred P1;\n\tWL_%=: \n\t"                     \
            "mbarrier.try_wait.parity.acquire.cta.shared::cta.b64 P1, [%0], %1, 0x989680;\n\t" \
            "@P1 bra.uni WD_%=;\n\tbra.uni WL_%=;\n\tWD_%=:\n\t}"             \
            :: "r"(_m), "r"(_p) : "memory");                                  \
    }                                                                         \
} while (0)
#define LDTM_X32(r, tmem_addr) \
    asm volatile("tcgen05.ld.sync.aligned.32x32b.x32.b32 " \
        "{%0, %1, %2, %3, %4, %5, %6, %7, %8, %9, %10, %11, %12, %13, %14, %15, " \
        "%16, %17, %18, %19, %20, %21, %22, %23, %24, %25, %26, %27, %28, %29, %30, %31}, [%32];" \
        : "=r"((r)[0]),  "=r"((r)[1]),  "=r"((r)[2]),  "=r"((r)[3]),  \
          "=r"((r)[4]),  "=r"((r)[5]),  "=r"((r)[6]),  "=r"((r)[7]),  \
          "=r"((r)[8]),  "=r"((r)[9]),  "=r"((r)[10]), "=r"((r)[11]), \
          "=r"((r)[12]), "=r"((r)[13]), "=r"((r)[14]), "=r"((r)[15]), \
          "=r"((r)[16]), "=r"((r)[17]), "=r"((r)[18]), "=r"((r)[19]), \
          "=r"((r)[20]), "=r"((r)[21]), "=r"((r)[22]), "=r"((r)[23]), \
          "=r"((r)[24]), "=r"((r)[25]), "=r"((r)[26]), "=r"((r)[27]), \
          "=r"((r)[28]), "=r"((r)[29]), "=r"((r)[30]), "=r"((r)[31]) \
        : "r"(tmem_addr))
#define STTM_X32(tmem_addr, r) \
    asm volatile("tcgen05.st.sync.aligned.32x32b.x32.b32 [%0], " \
        "{%1, %2, %3, %4, %5, %6, %7, %8, %9, %10, %11, %12, %13, %14, %15, %16, " \
        "%17, %18, %19, %20, %21, %22, %23, %24, %25, %26, %27, %28, %29, %30, %31, %32};" \
        :: "r"(tmem_addr), \
           "r"((r)[0]),  "r"((r)[1]),  "r"((r)[2]),  "r"((r)[3]),  \
           "r"((r)[4]),  "r"((r)[5]),  "r"((r)[6]),  "r"((r)[7]),  \
           "r"((r)[8]),  "r"((r)[9]),  "r"((r)[10]), "r"((r)[11]), \
           "r"((r)[12]), "r"((r)[13]), "r"((r)[14]), "r"((r)[15]), \
           "r"((r)[16]), "r"((r)[17]), "r"((r)[18]), "r"((r)[19]), \
           "r"((r)[20]), "r"((r)[21]), "r"((r)[22]), "r"((r)[23]), \
           "r"((r)[24]), "r"((r)[25]), "r"((r)[26]), "r"((r)[27]), \
           "r"((r)[28]), "r"((r)[29]), "r"((r)[30]), "r"((r)[31]) \
        : "memory")
#define CP_ASYNC16(smem, gptr) \
    asm volatile("cp.async.cg.shared.global [%0], [%1], 16;" \
                 :: "r"(smem), "l"(gptr) : "memory")
#define CP_COMMIT() asm volatile("cp.async.commit_group;" ::: "memory")
#define CP_WAIT(n)  asm volatile("cp.async.wait_group %0;" :: "n"(n) : "memory")

static constexpr uint64_t DESC_BASE_SW128 =
    (uint64_t(2) << 61) | (uint64_t(1) << 46) | (uint64_t(64) << 32) | (uint64_t(1) << 16);
#define MK_DESC(addr) (DESC_BASE_SW128 | ((uint64_t)((addr) >> 4) & 0x3FFF))
#define SWZ128(off) ((off) ^ (((off) >> 3) & 0x70))

#if TC_OK
__device__ __forceinline__ void mma_tf32_ss(uint32_t d, uint64_t ad, uint64_t bd,
                                            uint32_t idesc, uint32_t en) {
    asm volatile("{\n\t.reg .pred p;\n\tsetp.ne.u32 p, %5, 0;\n\t"
        "tcgen05.mma.cta_group::1.kind::tf32 [%0], %1, %2, %3, {%4, %4, %4, %4}, p;\n\t}"
        :: "r"(d), "l"(ad), "l"(bd), "r"(idesc), "r"(0u), "r"(en) : "memory");
}
__device__ __forceinline__ void mma_tf32_ts(uint32_t d, uint32_t a_tmem, uint64_t bd,
                                            uint32_t idesc, uint32_t en) {
    asm volatile("{\n\t.reg .pred p;\n\tsetp.ne.u32 p, %5, 0;\n\t"
        "tcgen05.mma.cta_group::1.kind::tf32 [%0], [%1], %2, %3, {%4, %4, %4, %4}, p;\n\t}"
        :: "r"(d), "r"(a_tmem), "l"(bd), "r"(idesc), "r"(0u), "r"(en) : "memory");
}
#endif

__device__ __forceinline__ float tf32r(float x) {
    uint32_t u;
    asm("cvt.rna.tf32.f32 %0, %1;" : "=r"(u) : "f"(x));
    return __uint_as_float(u);
}
__device__ __forceinline__ float ex2f(float x) {
    float y;
    asm("ex2.approx.f32 %0, %1;" : "=f"(y) : "f"(x));
    return y;
}

static constexpr uint32_t IDESC_N128 =
    (1u << 4) | (2u << 7) | (2u << 10) | (16u << 17) | (8u << 24);
static constexpr uint32_t IDESC_N64 =
    (1u << 4) | (2u << 7) | (2u << 10) | (8u << 17) | (8u << 24);

// (1/sqrt(64)) * log2(e)
#define QSCALE 0.18033688011112042f

__host__ __device__ __forceinline__ uint32_t blk_off(int r, int c) {
    return ((uint32_t)(r >> 7) * 32 + (uint32_t)(c >> 5)) * 16384u +
           SWZ128((uint32_t)((r & 127) << 7) + (uint32_t)((c & 31) << 2));
}

// ---------------- init / precvt ---------------------------------------------
__global__ void init_invf() {
    int j = threadIdx.x;
    double e = (double)(2 * j) / 64.0;
    g_invf[j] = (float)(1.0 / pow(10000.0, e));
}
__global__ __launch_bounds__(256) void init_tables() {
    int idx = blockIdx.x * blockDim.x + threadIdx.x;
    int j = idx >> 12;
    int s = idx & (SEQ - 1);
    float ang = (float)s * g_invf[j];
    float sn, cs;
    sincosf(ang, &sn, &cs);
    g_cosT[idx] = cs;
    g_sinT[idx] = sn;
}
__global__ __launch_bounds__(256) void precvt_all(
    const float* __restrict__ x,
    const float* __restrict__ Wq, const float* __restrict__ Wk,
    const float* __restrict__ Wv, const float* __restrict__ Wo,
    float* __restrict__ xt, float* __restrict__ Wt)
{
    int i = blockIdx.x * 256 + threadIdx.x;
    const float4* src;
    char* dstbase;
    int off;
    if (i < (1 << 20)) {
        src = (const float4*)x; dstbase = (char*)xt; off = i;
    } else {
        int k = i - (1 << 20);
        int w = k >> 18;
        off = k & ((1 << 18) - 1);
        src = (const float4*)(w == 0 ? Wq : w == 1 ? Wk : w == 2 ? Wv : Wo);
        dstbase = (char*)(Wt + (size_t)w * DM * DM);
    }
    float4 v = src[off];
    v.x = tf32r(v.x); v.y = tf32r(v.y); v.z = tf32r(v.z); v.w = tf32r(v.w);
    int r = off >> 8;
    int c4 = off & 255;
    uint32_t byte = ((uint32_t)(r >> 7) * 32 + (uint32_t)(c4 >> 3)) * 16384u +
                    SWZ128((uint32_t)((r & 127) << 7) + (uint32_t)((c4 & 7) << 4));
    *(float4*)(dstbase + byte) = v;
}

// ---------------------------------------------------------------------------
// Fused Q+K projection GEMM (R14-proven, unchanged).
// ---------------------------------------------------------------------------
#define QK_SMEM 99840

__global__ __launch_bounds__(256, 2) void gemm_qk(
    const float* __restrict__ A, const float* __restrict__ Bq,
    const float* __restrict__ Bk,
    const float* __restrict__ biasq, const float* __restrict__ biask,
    float* __restrict__ Cq, float* __restrict__ Ck,
    const float* __restrict__ cosT, const float* __restrict__ sinT)
{
#if TC_OK
    extern __shared__ char sm[];
    const uint32_t sbase = smem_u32(sm);
    const uint32_t tile0 = (sbase + 64 + 1023) & ~1023u;

    const int tid = threadIdx.x;
    const int wid = tid >> 5;
    const int row0 = blockIdx.y << 7;
    const int col0 = blockIdx.x << 7;

    if (wid == 0) TC_ALLOC(sbase, 256);
    if (tid == 0) { MBAR_INIT(sbase + 8, 1); MBAR_INIT(sbase + 16, 1); }
    __syncthreads();
    uint32_t tmem;
    asm volatile("ld.shared.b32 %0, [%1];" : "=r"(tmem) : "r"(sbase));
    if (wid == 0) TC_RELINQ();
    const uint32_t tmQ = tmem;
    const uint32_t tmK = tmem + 128;

    const char* Asrc  = (const char*)A  + (size_t)(row0 >> 7) * 32 * 16384;
    const char* Bqsrc = (const char*)Bq + (size_t)(col0 >> 7) * 32 * 16384;
    const char* Bksrc = (const char*)Bk + (size_t)(col0 >> 7) * 32 * 16384;

    for (int kc = 0; kc < 33; kc++) {
        if (kc < 32) {
            const int s = kc & 1;
            if (kc >= 2) MBAR_WAIT(sbase + 8 + s * 8, ((kc - 2) / 2) & 1);
            const uint32_t sb = tile0 + s * 49152;
            const char* Ag  = Asrc  + (size_t)kc * 16384;
            const char* Bqg = Bqsrc + (size_t)kc * 16384;
            const char* Bkg = Bksrc + (size_t)kc * 16384;
#pragma unroll
            for (int t = 0; t < 4; t++) {
                uint32_t off = (uint32_t)tid * 16 + t * 4096;
                CP_ASYNC16(sb + off, Ag + off);
                CP_ASYNC16(sb + 16384 + off, Bqg + off);
                CP_ASYNC16(sb + 32768 + off, Bkg + off);
            }
            CP_COMMIT();
        }
        if (kc >= 1) {
            const int j = kc - 1;
            const int sj = j & 1;
            if (kc < 32) CP_WAIT(1);
            else CP_WAIT(0);
            __syncthreads();
            if (wid == 0 && elect_one()) {
                FENCE_ASYNC();
                uint64_t ad  = MK_DESC(tile0 + sj * 49152);
                uint64_t bdq = MK_DESC(tile0 + sj * 49152 + 16384);
                uint64_t bdk = MK_DESC(tile0 + sj * 49152 + 32768);
#pragma unroll
                for (int ks = 0; ks < 4; ks++)
                    mma_tf32_ss(tmQ, ad + ks * 2, bdq + ks * 2, IDESC_N128,
                                (j > 0) || (ks > 0));
#pragma unroll
                for (int ks = 0; ks < 4; ks++)
                    mma_tf32_ss(tmK, ad + ks * 2, bdk + ks * 2, IDESC_N128,
                                (j > 0) || (ks > 0));
                TC_COMMIT(sbase + 8 + sj * 8);
            }
        }
    }
    MBAR_WAIT(sbase + 8, 1);
    MBAR_WAIT(sbase + 16, 1);
    TC_FENCE_AFTER();

    if (tid < 128) {
        const int lid = tid & 31;
        const int w = tid >> 5;
        const int row = row0 + w * 32 + lid;
#pragma unroll
        for (int m = 0; m < 2; m++) {
            const uint32_t tm = m ? tmK : tmQ;
            const float* bias = m ? biask : biasq;
            float* C = m ? Ck : Cq;
            const float sc = m ? 1.0f : QSCALE;
#pragma unroll
            for (int half = 0; half < 2; half++) {
                uint32_t rr[64];
                LDTM_X32(rr, tm + half * 64);
                LDTM_X32(rr + 32, tm + half * 64 + 32);
                TC_WAIT_LD();
                const int gc0 = col0 + half * 64;
                float v[64];
#pragma unroll
                for (int j = 0; j < 64; j++)
                    v[j] = __uint_as_float(rr[j]) + __ldg(&bias[gc0 + j]);
#pragma unroll
                for (int j = 0; j < 32; j++) {
                    float cs = __ldg(&cosT[j * SEQ + row]);
                    float sn = __ldg(&sinT[j * SEQ + row]);
                    float a = v[j], b2 = v[j + 32];
                    v[j]      = a * cs - b2 * sn;
                    v[j + 32] = b2 * cs + a * sn;
                }
#pragma unroll
                for (int j = 0; j < 64; j++) v[j] = tf32r(v[j] * sc);
                int hh = gc0 >> 6;
                float* dst = C + ((size_t)hh * SEQ + row) * HD;
#pragma unroll
                for (int j4 = 0; j4 < 64; j4 += 4)
                    *(float4*)(dst + j4) = make_float4(v[j4], v[j4+1], v[j4+2], v[j4+3]);
            }
        }
    }
    __syncthreads();
    if (tid == 0) { MBAR_INVAL(sbase + 8); MBAR_INVAL(sbase + 16); }
    __syncthreads();
    if (wid == 0) TC_DEALLOC(tmem, 256);
#else
    const int tid = threadIdx.x;
    const int row0 = blockIdx.y << 7;
    const int col0 = blockIdx.x << 7;
    for (int e = tid; e < 128 * 128; e += 256) {
        int r = row0 + (e >> 7);
        int c = col0 + (e & 127);
        for (int m = 0; m < 2; m++) {
            const float* B = m ? Bk : Bq;
            const float* bias = m ? biask : biasq;
            float* C = m ? Ck : Cq;
            float sc = m ? 1.0f : QSCALE;
            int j = c & 63;
            int jp = (j < 32) ? j + 32 : j - 32;
            int cp = (c & ~63) | jp;
            float acc = bias[c], acc2 = bias[cp];
            for (int k = 0; k < DM; k++) {
                float av = *(const float*)((const char*)A + blk_off(r, k));
                acc  += av * *(const float*)((const char*)B + blk_off(c, k));
                acc2 += av * *(const float*)((const char*)B + blk_off(cp, k));
            }
            int f = (j < 32) ? j : j - 32;
            float cs = cosT[f * SEQ + r], sn = sinT[f * SEQ + r];
            float outv = (j < 32) ? (acc * cs - acc2 * sn) : (acc * cs + acc2 * sn);
            C[(((size_t)(c >> 6) * SEQ + r) * HD) + (c & 63)] = tf32r(outv * sc);
        }
    }
#endif
}

// ---------------------------------------------------------------------------
// tcgen05 tf32 GEMM (V projection + output proj), R13-proven, unchanged.
// ---------------------------------------------------------------------------
#define GEMM_SMEM 100352

__global__ __launch_bounds__(256, 2) void gemm_tc(
    const float* __restrict__ A, const float* __restrict__ B,
    const float* __restrict__ bias, float* __restrict__ C, int mode, float sc,
    const float* __restrict__ cosT, const float* __restrict__ sinT)
{
#if TC_OK
    extern __shared__ char sm[];
    const uint32_t sbase = smem_u32(sm);
    const uint32_t tile0 = (sbase + 64 + 1023) & ~1023u;

    const int tid = threadIdx.x;
    const int wid = tid >> 5;
    const int row0 = blockIdx.y << 7;
    const int col0 = blockIdx.x << 7;

    if (wid == 0) TC_ALLOC(sbase, 128);
    if (tid == 0) {
        MBAR_INIT(sbase + 8, 1);  MBAR_INIT(sbase + 16, 1);
        MBAR_INIT(sbase + 24, 1);
    }
    __syncthreads();
    uint32_t tmem;
    asm volatile("ld.shared.b32 %0, [%1];" : "=r"(tmem) : "r"(sbase));
    if (wid == 0) TC_RELINQ();

    const char* Asrc = (const char*)A + (size_t)(row0 >> 7) * 32 * 16384;
    const char* Bsrc = (const char*)B + (size_t)(col0 >> 7) * 32 * 16384;

    for (int kc = 0; kc < 34; kc++) {
        if (kc < 32) {
            const int s = kc % 3;
            if (kc >= 3) MBAR_WAIT(sbase + 8 + s * 8, ((kc - 3) / 3) & 1);
            const uint32_t sA = tile0 + s * 32768;
            const char* Ag = Asrc + (size_t)kc * 16384;
            const char* Bg = Bsrc + (size_t)kc * 16384;
#pragma unroll
            for (int t = 0; t < 4; t++) {
                uint32_t off = (uint32_t)tid * 16 + t * 4096;
                CP_ASYNC16(sA + off, Ag + off);
                CP_ASYNC16(sA + 16384 + off, Bg + off);
            }
            CP_COMMIT();
        }
        if (kc >= 2) {
            const int j = kc - 2;
            const int sj = j % 3;
            if (kc < 32) CP_WAIT(2);
            else if (kc == 32) CP_WAIT(1);
            else CP_WAIT(0);
            __syncthreads();
            if (wid == 0 && elect_one()) {
                FENCE_ASYNC();
                uint64_t ad = MK_DESC(tile0 + sj * 32768);
                uint64_t bd = MK_DESC(tile0 + sj * 32768 + 16384);
#pragma unroll
                for (int ks = 0; ks < 4; ks++)
                    mma_tf32_ss(tmem, ad + ks * 2, bd + ks * 2, IDESC_N128,
                                (j > 0) || (ks > 0));
                TC_COMMIT(sbase + 8 + sj * 8);
            }
        }
    }
    MBAR_WAIT(sbase + 8, 0);
    MBAR_WAIT(sbase + 16, 0);
    MBAR_WAIT(sbase + 24, 1);
    TC_FENCE_AFTER();

    if (tid < 128) {
        const int lid = tid & 31;
        const int w = tid >> 5;
        const int row = row0 + w * 32 + lid;
        const bool rope = (mode & 2) != 0;
        const bool rnd  = (mode & 8) != 0;
        const bool scl  = (mode & 16) != 0;
#pragma unroll
        for (int half = 0; half < 2; half++) {
            uint32_t rr[64];
            LDTM_X32(rr, tmem + half * 64);
            LDTM_X32(rr + 32, tmem + half * 64 + 32);
            TC_WAIT_LD();
            const int gc0 = col0 + half * 64;
            float v[64];
#pragma unroll
            for (int j = 0; j < 64; j++)
                v[j] = __uint_as_float(rr[j]) + __ldg(&bias[gc0 + j]);
            if (rope) {
#pragma unroll
                for (int j = 0; j < 32; j++) {
                    float cs = __ldg(&cosT[j * SEQ + row]);
                    float sn = __ldg(&sinT[j * SEQ + row]);
                    float a = v[j], b2 = v[j + 32];
                    v[j]      = a * cs - b2 * sn;
                    v[j + 32] = b2 * cs + a * sn;
                }
            }
            if (scl) {
#pragma unroll
                for (int j = 0; j < 64; j++) v[j] *= sc;
            }
            if (rnd) {
#pragma unroll
                for (int j = 0; j < 64; j++) v[j] = tf32r(v[j]);
            }
            if (mode & 4) {
                int hh = gc0 >> 6;
                float* dst = C + (size_t)(hh * HD) * SEQ + row;
#pragma unroll
                for (int j = 0; j < 64; j++)
                    dst[(size_t)j * SEQ] = v[j];
            } else if (mode & 1) {
                int hh = gc0 >> 6;
                float* dst = C + ((size_t)hh * SEQ + row) * HD;
#pragma unroll
                for (int j4 = 0; j4 < 64; j4 += 4)
                    *(float4*)(dst + j4) = make_float4(v[j4], v[j4+1], v[j4+2], v[j4+3]);
            } else {
                float* dst = C + (size_t)row * DM + gc0;
#pragma unroll
                for (int j4 = 0; j4 < 64; j4 += 4)
                    *(float4*)(dst + j4) = make_float4(v[j4], v[j4+1], v[j4+2], v[j4+3]);
            }
        }
    }
    __syncthreads();
    if (tid == 0) {
        MBAR_INVAL(sbase + 8);  MBAR_INVAL(sbase + 16);
        MBAR_INVAL(sbase + 24);
    }
    __syncthreads();
    if (wid == 0) TC_DEALLOC(tmem, 128);
#else
    const int tid = threadIdx.x;
    const int row0 = blockIdx.y << 7;
    const int col0 = blockIdx.x << 7;
    for (int e = tid; e < 128 * 128; e += 256) {
        int r = row0 + (e >> 7);
        int c = col0 + (e & 127);
        float acc = bias[c];
        for (int k = 0; k < DM; k++)
            acc += *(const float*)((const char*)A + blk_off(r, k)) *
                   *(const float*)((const char*)B + blk_off(c, k));
        float outv = acc;
        if (mode & 2) {
            int j = c & 63;
            int jp = (j < 32) ? j + 32 : j - 32;
            int cp = (c & ~63) | jp;
            float acc2 = bias[cp];
            for (int k = 0; k < DM; k++)
                acc2 += *(const float*)((const char*)A + blk_off(r, k)) *
                        *(const float*)((const char*)B + blk_off(cp, k));
            int f = (j < 32) ? j : j - 32;
            float cs = cosT[f * SEQ + r], sn = sinT[f * SEQ + r];
            outv = (j < 32) ? (acc * cs - acc2 * sn) : (acc * cs + acc2 * sn);
        }
        if (mode & 16) outv *= sc;
        if (mode & 8)  outv = tf32r(outv);
        if (mode & 4)      C[(size_t)((c >> 6) * HD + (c & 63)) * SEQ + r] = outv;
        else if (mode & 1) C[(((size_t)(c >> 6) * SEQ + r) * HD) + (c & 63)] = outv;
        else               C[(size_t)r * DM + c] = outv;
    }
#endif
}

// ---------------------------------------------------------------------------
// tcgen05 flash attention, K-tile = 64 keys -> 2 CTAs/SM.
// Per-CTA TMEM 256 cols: S0 @0 | S1 @64 | O @128 | P @192.
// smem ~98KB: Q 32K | K 2x16K | V 2x16K. Same loop/barrier/prefetch shape
// as the proven R13/R14 kernel; nt = 2*qt+2; two masked diag tiles.
// ---------------------------------------------------------------------------
#if TC_OK
#define ATTN_SMEM 100352
#else
#define ATTN_SMEM 0
#endif

__global__ __launch_bounds__(256, 2) void attn_tc(
    const float* __restrict__ Q, const float* __restrict__ K,
    const float* __restrict__ Vt, float* __restrict__ Og)
{
#if TC_OK
    extern __shared__ char sm[];
    const uint32_t sbase = smem_u32(sm);
    float* lsum = (float*)(sm + 64);                 // [2][128]
    const uint32_t tile0 = (sbase + 1088 + 1023) & ~1023u;
    const uint32_t QS  = tile0;                 // 32K
    const uint32_t KS0 = tile0 + 32768;         // K[b] = KS0 + b*16384
    const uint32_t VS0 = tile0 + 65536;         // V[b] = VS0 + b*16384

    const int qt = (int)gridDim.x - 1 - (int)blockIdx.x;  // heavy first
    const int h  = blockIdx.y;
    const int nt = 2 * qt + 2;
    const int tid = threadIdx.x;
    const int wid = tid >> 5;
    const int lane = tid & 31;
    const int g = wid >> 2;              // column group 0/1 (32 cols each)
    const int rowl = ((wid & 3) << 5) + lane;
    const int cbase = g << 5;
    const uint32_t laneoff = ((uint32_t)(wid & 3)) << 21;

    if (wid == 0) TC_ALLOC(sbase, 256);
    if (tid == 0) {
        MBAR_INIT(sbase + 8, 1);   // mS0
        MBAR_INIT(sbase + 16, 1);  // mS1
        MBAR_INIT(sbase + 24, 1);  // mPV
    }
    __syncthreads();
    uint32_t tmem;
    asm volatile("ld.shared.b32 %0, [%1];" : "=r"(tmem) : "r"(sbase));
    if (wid == 0) TC_RELINQ();
    const uint32_t tmO = tmem + 128;
    const uint32_t tmP = tmem + 192;

    const float* Qg  = Q + ((size_t)h * SEQ + (size_t)qt * 128) * HD;
    const float* Kg0 = K + (size_t)h * SEQ * HD;
    const float* Vg0 = Vt + (size_t)(h * HD) * SEQ;
    const uint64_t adQ = MK_DESC(QS);

    // ---- prologue: Q (32K), K(0) (16K), V(0) (16K); then K(1)
#pragma unroll
    for (int i = 0; i < 8; i++) {
        int idx = tid + i * 256;
        int r = idx >> 4, c4 = idx & 15;
        uint32_t off = ((uint32_t)(c4 >> 3) * 16384) +
                       SWZ128((uint32_t)(r * 128 + (c4 & 7) * 16));
        CP_ASYNC16(QS + off, Qg + (size_t)r * HD + c4 * 4);
    }
#pragma unroll
    for (int i = 0; i < 4; i++) {
        int idx = tid + i * 256;
        int r = idx >> 4, c4 = idx & 15;   // r = key 0..63, c4 = dim/4
        uint32_t off = ((uint32_t)(c4 >> 3) * 8192) +
                       SWZ128((uint32_t)(r * 128 + (c4 & 7) * 16));
        CP_ASYNC16(KS0 + off, Kg0 + (size_t)r * HD + c4 * 4);
    }
#pragma unroll
    for (int i = 0; i < 4; i++) {
        int idx = tid + i * 256;
        int r = idx >> 4, c4 = idx & 15;   // r = dim 0..63, c4 = key/4
        uint32_t off = ((uint32_t)(c4 >> 3) * 8192) +
                       SWZ128((uint32_t)(r * 128 + (c4 & 7) * 16));
        CP_ASYNC16(VS0 + off, Vg0 + (size_t)r * SEQ + c4 * 4);
    }
    CP_COMMIT();
    {   // K(1) (nt >= 2 always)
        const float* Kg = Kg0 + (size_t)64 * HD;
#pragma unroll
        for (int i = 0; i < 4; i++) {
            int idx = tid + i * 256;
            int r = idx >> 4, c4 = idx & 15;
            uint32_t off = ((uint32_t)(c4 >> 3) * 8192) +
                           SWZ128((uint32_t)(r * 128 + (c4 & 7) * 16));
            CP_ASYNC16(KS0 + 16384 + off, Kg + (size_t)r * HD + c4 * 4);
        }
        CP_COMMIT();
    }
    CP_WAIT(0);
    __syncthreads();
    if (wid == 0 && elect_one()) {
        FENCE_ASYNC();
        uint64_t bd = MK_DESC(KS0);
#pragma unroll
        for (int ks = 0; ks < 8; ks++)
            mma_tf32_ss(tmem, adQ + (ks >> 2) * 1024 + (ks & 3) * 2,
                        bd + (ks >> 2) * 512 + (ks & 3) * 2, IDESC_N64, ks > 0);
        TC_COMMIT(sbase + 8);
    }

    float lp = 0.0f;
    const int diag0 = 2 * qt;   // first masked tile

    for (int kt = 0; kt < nt; kt++) {
        const int b = kt & 1;
        const uint32_t tmSb = tmem + (uint32_t)b * 64;

        MBAR_WAIT(sbase + 8 + b * 8, (kt >> 1) & 1);   // S(kt) ready
        TC_FENCE_AFTER();

        // issue S(kt+1) now (overlaps softmax below)
        if (kt + 1 < nt && wid == 0 && elect_one()) {
            FENCE_ASYNC();
            uint64_t bd = MK_DESC(KS0 + (uint32_t)(b ^ 1) * 16384);
            uint32_t d = tmem + (uint32_t)(b ^ 1) * 64;
#pragma unroll
            for (int ks = 0; ks < 8; ks++)
                mma_tf32_ss(d, adQ + (ks >> 2) * 1024 + (ks & 3) * 2,
                            bd + (ks >> 2) * 512 + (ks & 3) * 2,
                            IDESC_N64, ks > 0);
            TC_COMMIT(sbase + 8 + (b ^ 1) * 8);
        }

        // prefetch K(kt+2) into Kbuf[b]
        if (kt + 2 < nt) {
            const float* Kg = Kg0 + (size_t)(kt + 2) * 64 * HD;
#pragma unroll
            for (int i = 0; i < 4; i++) {
                int idx = tid + i * 256;
                int r = idx >> 4, c4 = idx & 15;
                uint32_t off = ((uint32_t)(c4 >> 3) * 8192) +
                               SWZ128((uint32_t)(r * 128 + (c4 & 7) * 16));
                CP_ASYNC16(KS0 + (uint32_t)b * 16384 + off,
                           Kg + (size_t)r * HD + c4 * 4);
            }
            CP_COMMIT();
        }

        // ---- softmax: one 32-col group per thread
        uint32_t rr[32];
        LDTM_X32(rr, tmSb + cbase);
        TC_WAIT_LD();

        if (kt < diag0) {       // fast path: no masking
#pragma unroll
            for (int j = 0; j < 32; j++) {
                float e = tf32r(ex2f(__uint_as_float(rr[j])));
                rr[j] = __float_as_uint(e);
                lp += e;
            }
        } else {                // masked tiles (kt = 2qt, 2qt+1)
            const int koff = (kt - diag0) << 6;
#pragma unroll
            for (int j = 0; j < 32; j++) {
                float e = ex2f(__uint_as_float(rr[j]));
                e = (koff + cbase + j > rowl) ? 0.0f : tf32r(e);
                rr[j] = __float_as_uint(e);
                lp += e;
            }
        }

        // PV(kt-1) done -> P TMEM free
        if (kt > 0) MBAR_WAIT(sbase + 24, (kt - 1) & 1);
        STTM_X32(tmP + laneoff + cbase, rr);
        TC_WAIT_ST();

        // prefetch V(kt+1) into Vbuf[b^1]
        if (kt + 1 < nt) {
            const float* Vg = Vg0 + (size_t)(kt + 1) * 64;
            const uint32_t vdst = VS0 + (uint32_t)(b ^ 1) * 16384;
#pragma unroll
            for (int i = 0; i < 4; i++) {
                int idx = tid + i * 256;
                int r = idx >> 4, c4 = idx & 15;
                uint32_t off = ((uint32_t)(c4 >> 3) * 8192) +
                               SWZ128((uint32_t)(r * 128 + (c4 & 7) * 16));
                CP_ASYNC16(vdst + off, Vg + (size_t)r * SEQ + c4 * 4);
            }
            CP_COMMIT();
        }

        TC_FENCE_BEFORE();
        if (kt + 1 < nt) CP_WAIT(1);
        else CP_WAIT(0);
        __syncthreads();

        if (wid == 0 && elect_one()) {
            FENCE_ASYNC();
            uint64_t vd = MK_DESC(VS0 + (uint32_t)b * 16384);
#pragma unroll
            for (int ks = 0; ks < 8; ks++)
                mma_tf32_ts(tmO, tmP + ks * 8,
                            vd + (ks >> 2) * 512 + (ks & 3) * 2,
                            IDESC_N64, (kt > 0) || (ks > 0));
            TC_COMMIT(sbase + 24);
        }
    }

    // ---- epilogue: combine l, read O, blocked store into g_AO
    lsum[g * 128 + rowl] = lp;
    MBAR_WAIT(sbase + 24, (nt - 1) & 1);
    TC_FENCE_AFTER();
    __syncthreads();
    float l = lsum[rowl] + lsum[128 + rowl];
    {
        uint32_t rr[32];
        LDTM_X32(rr, tmO + g * 32);
        TC_WAIT_LD();
        float inv = 1.0f / l;
        char* dstb = (char*)Og + ((size_t)qt * 32 + h * 2 + g) * 16384;
#pragma unroll
        for (int j4 = 0; j4 < 8; j4++) {
            float4 v = make_float4(
                tf32r(__uint_as_float(rr[j4*4+0]) * inv),
                tf32r(__uint_as_float(rr[j4*4+1]) * inv),
                tf32r(__uint_as_float(rr[j4*4+2]) * inv),
                tf32r(__uint_as_float(rr[j4*4+3]) * inv));
            *(float4*)(dstb + SWZ128((uint32_t)(rowl * 128 + j4 * 16))) = v;
        }
    }
    __syncthreads();
    if (tid == 0) {
        MBAR_INVAL(sbase + 8); MBAR_INVAL(sbase + 16); MBAR_INVAL(sbase + 24);
    }
    __syncthreads();
    if (wid == 0) TC_DEALLOC(tmem, 256);
#else
    const int qt = (int)gridDim.x - 1 - (int)blockIdx.x;
    const int h = blockIdx.y;
    const int tid = threadIdx.x;
    for (int r = tid; r < 128; r += 256) {
        int row = qt * 128 + r;
        const float* q = Q + ((size_t)h * SEQ + row) * HD;
        float l = 0.0f, o[HD];
        for (int d = 0; d < HD; d++) o[d] = 0.0f;
        for (int key = 0; key <= row; key++) {
            const float* kp = K + ((size_t)h * SEQ + key) * HD;
            float s = 0.0f;
            for (int d = 0; d < HD; d++) s += q[d] * kp[d];
            float p = exp2f(s);
            l += p;
            for (int d = 0; d < HD; d++)
                o[d] += p * Vt[(size_t)(h * HD + d) * SEQ + key];
        }
        for (int d = 0; d < HD; d++) {
            int c = h * HD + d;
            *(float*)((char*)Og + blk_off(row, c)) = tf32r(o[d] / l);
        }
    }
#endif
}

// ---------------------------------------------------------------------------
extern "C" void kernel_launch(void* const* d_in, const int* in_sizes, int n_in,
                              void* d_out, int out_size)
{
    (void)in_sizes; (void)n_in; (void)out_size;
    const float* x  = (const float*)d_in[0];
    const float* Wq = (const float*)d_in[1];
    const float* bq = (const float*)d_in[2];
    const float* Wk = (const float*)d_in[3];
    const float* bk = (const float*)d_in[4];
    const float* Wv = (const float*)d_in[5];
    const float* bv = (const float*)d_in[6];
    const float* Wo = (const float*)d_in[7];
    const float* bo = (const float*)d_in[8];
    float* out = (float*)d_out;

    float *Qp, *Kp, *Vp, *AOp, *cosT, *sinT, *xt, *Wt;
    cudaGetSymbolAddress((void**)&Qp, g_Q);
    cudaGetSymbolAddress((void**)&Kp, g_K);
    cudaGetSymbolAddress((void**)&Vp, g_V);
    cudaGetSymbolAddress((void**)&AOp, g_AO);
    cudaGetSymbolAddress((void**)&cosT, g_cosT);
    cudaGetSymbolAddress((void**)&sinT, g_sinT);
    cudaGetSymbolAddress((void**)&xt, g_xt);
    cudaGetSymbolAddress((void**)&Wt, g_Wt);

    cudaFuncSetAttribute(gemm_tc, cudaFuncAttributeMaxDynamicSharedMemorySize,
                         GEMM_SMEM);
    cudaFuncSetAttribute(gemm_qk, cudaFuncAttributeMaxDynamicSharedMemorySize,
                         QK_SMEM);
    cudaFuncSetAttribute(attn_tc, cudaFuncAttributeMaxDynamicSharedMemorySize,
                         ATTN_SMEM);

    init_invf<<<1, 32>>>();
    init_tables<<<(32 * SEQ) / 256, 256>>>();
    precvt_all<<<8192, 256>>>(x, Wq, Wk, Wv, Wo, xt, Wt);

    dim3 gg(DM / 128, SEQ / 128);   // (8, 32) = 256 CTAs, 2/SM, one wave
    gemm_qk<<<gg, 256, QK_SMEM>>>(xt, Wt + 0 * DM * DM, Wt + 1 * DM * DM,
                                  bq, bk, Qp, Kp, cosT, sinT);
    gemm_tc<<<gg, 256, GEMM_SMEM>>>(xt, Wt + 2 * DM * DM, bv, Vp, 12, 1.0f, cosT, sinT);

    attn_tc<<<dim3(SEQ / 128, NH), 256, ATTN_SMEM>>>(Qp, Kp, Vp, AOp);

    gemm_tc<<<gg, 256, GEMM_SMEM>>>(AOp, Wt + 3 * DM * DM, bo, out, 0, 1.0f, cosT, sinT);
}